// round 2
// baseline (speedup 1.0000x reference)
#include <cuda_runtime.h>
#include <cuda_bf16.h>

// DeformableConv2d fused kernel v2, sm_103a.
//
// x[8,64,128,128], offset_w[1152,1,3,3], offset_b[1152],
// deform_w[64,64,3,3], deform_b[64] -> out[8,64,128,128] fp32
//
// Key math: softmax outputs dy,dx in (0,1) with integer sample base, so
// bilinear corners live in a fixed 4x4 zero-padded patch around each pixel.
//
// v2 changes vs v1 (1278us):
//  - exp values recomputed in pass B instead of stored (smem 206KB -> 105KB,
//    2 CTAs/SM instead of 1)
//  - phase-5 GEMM reads weights from a pre-transposed global wtT[ck][o]
//    (LDG.128, L1/L2-resident) -> no smem weight staging, no barriers in the
//    2304-FFMA mainloop
//  - samp stored transposed [p][ck] so the mainloop uses LDS.128

#define Bq 8
#define Cc 64
#define Hh 128
#define Ww 128
#define CO 64
#define Pp 16           // positions (w) per CTA

// smem layout (floats)
#define SM_SOW   0                    // [64][18][10] {w[9],bias}   = 11520
#define SM_PATCH 11520                // [64][4][20]                = 5120
#define SM_SAMP  (11520+5120)         // samp_t [16][592]           = 9472
#define SM_RED   (SM_SAMP+9472)       // [8][16]                    = 128
#define SM_INVS  (SM_RED+128)         // [16]                       = 16
#define SM_TOTAL (SM_INVS+16)
#define SMEM_BYTES (SM_TOTAL * 4)     // 105,056 B -> 2 CTAs/SM

#define SROW 592                      // samp_t row stride (576 + 16 pad)

__device__ float g_wtT[576 * 64];     // wtT[ck][o] = deform_w[o][ck]

__global__ void transpose_w_kernel(const float* __restrict__ dw)
{
    int i = blockIdx.x * 256 + threadIdx.x;
    if (i < 576 * 64) {
        int ck = i >> 6, o = i & 63;
        g_wtT[i] = dw[o * 576 + ck];
    }
}

__global__ __launch_bounds__(256, 2)
void deform_fused_kernel(const float* __restrict__ x,
                         const float* __restrict__ ow,
                         const float* __restrict__ obv,
                         const float* __restrict__ db,
                         float* __restrict__ out)
{
    extern __shared__ float sm[];
    float* sow   = sm + SM_SOW;
    float* patch = sm + SM_PATCH;
    float* samp  = sm + SM_SAMP;
    float* red   = sm + SM_RED;
    float* invS  = sm + SM_INVS;

    const int t  = threadIdx.x;
    const int w0 = blockIdx.x * Pp;
    const int h  = blockIdx.y;
    const int b  = blockIdx.z;

    // ---- Phase 0: stage offset weights {w[9],bias} rows + x patch ----
    for (int i = t; i < 11520; i += 256) {
        int cj = i / 10, m = i - cj * 10;
        sow[i] = (m < 9) ? __ldg(&ow[cj * 9 + m]) : __ldg(&obv[cj]);
    }
    {
        const float* xb = x + (size_t)b * Cc * Hh * Ww;
        for (int i = t; i < 5120; i += 256) {
            int c   = i / 80;
            int r2  = i - c * 80;
            int r   = r2 / 20;
            int col = r2 - r * 20;
            int gy = h - 1 + r;
            int gx = w0 - 1 + col;
            float v = 0.0f;
            if (gy >= 0 && gy < Hh && gx >= 0 && gx < Ww)
                v = xb[(size_t)c * (Hh * Ww) + gy * Ww + gx];
            patch[i] = v;
        }
    }
    __syncthreads();

    // thread mapping for phases A/B: channel c, 4 positions p0..p0+3
    const int c  = t >> 2;
    const int p0 = (t & 3) * 4;

    // patch values rows 0..3, cols p0..p0+6 -> registers, reused in A and B
    float pv[4][7];
    #pragma unroll
    for (int r = 0; r < 4; r++)
        #pragma unroll
        for (int s = 0; s < 7; s++)
            pv[r][s] = patch[(c * 4 + r) * 20 + p0 + s];

    const float* wc = sow + c * 180;

    // ---- Pass A: conv -> exp -> per-position partial sums ----
    float sums[4] = {0.f, 0.f, 0.f, 0.f};
    #pragma unroll
    for (int j = 0; j < 18; j++) {
        float2 wA = *(const float2*)(wc + j * 10 + 0);
        float2 wB = *(const float2*)(wc + j * 10 + 2);
        float2 wC = *(const float2*)(wc + j * 10 + 4);
        float2 wD = *(const float2*)(wc + j * 10 + 6);
        float2 wE = *(const float2*)(wc + j * 10 + 8);
        float w9[9] = {wA.x, wA.y, wB.x, wB.y, wC.x, wC.y, wD.x, wD.y, wE.x};
        float bias = wE.y;
        float e[4] = {bias, bias, bias, bias};
        #pragma unroll
        for (int r = 0; r < 3; r++)
            #pragma unroll
            for (int s = 0; s < 3; s++) {
                float wv = w9[r * 3 + s];
                #pragma unroll
                for (int q = 0; q < 4; q++)
                    e[q] += wv * pv[r][s + q];
            }
        #pragma unroll
        for (int q = 0; q < 4; q++)
            sums[q] += __expf(e[q]);
    }
    // reduce over the 8 channels within each warp (lanes differ in bits 2..4)
    #pragma unroll
    for (int off = 4; off <= 16; off <<= 1)
        #pragma unroll
        for (int q = 0; q < 4; q++)
            sums[q] += __shfl_xor_sync(0xffffffffu, sums[q], off);
    {
        int lane = t & 31, warp = t >> 5;
        if (lane < 4) {
            #pragma unroll
            for (int q = 0; q < 4; q++)
                red[warp * 16 + lane * 4 + q] = sums[q];
        }
    }
    __syncthreads();
    if (t < 16) {
        float s = 0.f;
        #pragma unroll
        for (int w = 0; w < 8; w++) s += red[w * 16 + t];
        invS[t] = 1.0f / s;
    }
    __syncthreads();

    float4 iv4 = *(const float4*)&invS[p0];
    float iv[4] = {iv4.x, iv4.y, iv4.z, iv4.w};

    // ---- Pass B: recompute conv/exp, bilinear sample -> samp_t[p][ck] ----
    #pragma unroll
    for (int k = 0; k < 9; k++) {
        const int ky = k / 3, kx = k % 3;
        float ey[4], ex[4];
        #pragma unroll
        for (int half = 0; half < 2; half++) {
            int j = 2 * k + half;
            float2 wA = *(const float2*)(wc + j * 10 + 0);
            float2 wB = *(const float2*)(wc + j * 10 + 2);
            float2 wC = *(const float2*)(wc + j * 10 + 4);
            float2 wD = *(const float2*)(wc + j * 10 + 6);
            float2 wE = *(const float2*)(wc + j * 10 + 8);
            float w9[9] = {wA.x, wA.y, wB.x, wB.y, wC.x, wC.y, wD.x, wD.y, wE.x};
            float bias = wE.y;
            float e[4] = {bias, bias, bias, bias};
            #pragma unroll
            for (int r = 0; r < 3; r++)
                #pragma unroll
                for (int s = 0; s < 3; s++) {
                    float wv = w9[r * 3 + s];
                    #pragma unroll
                    for (int q = 0; q < 4; q++)
                        e[q] += wv * pv[r][s + q];
                }
            #pragma unroll
            for (int q = 0; q < 4; q++) {
                if (half == 0) ey[q] = e[q]; else ex[q] = e[q];
            }
        }
        #pragma unroll
        for (int q = 0; q < 4; q++) {
            float dy = __expf(ey[q]) * iv[q];
            float dx = __expf(ex[q]) * iv[q];
            float a00 = pv[ky][q + kx],     a01 = pv[ky][q + kx + 1];
            float a10 = pv[ky + 1][q + kx], a11 = pv[ky + 1][q + kx + 1];
            float top = a00 + dx * (a01 - a00);
            float bot = a10 + dx * (a11 - a10);
            samp[(p0 + q) * SROW + c * 9 + k] = top + dy * (bot - top);
        }
    }
    __syncthreads();

    // ---- Phase 5: out[o][p] = sum_ck wtT[ck][o] * samp_t[p][ck] ----
    // thread: 4 outputs o0..o0+3, one position p. No barriers, no smem staging.
    {
        const int o0 = (t & 15) * 4;
        const int p  = t >> 4;
        const float* srow = samp + p * SROW;
        const float* wt   = g_wtT + o0;

        float acc0 = 0.f, acc1 = 0.f, acc2 = 0.f, acc3 = 0.f;
        #pragma unroll 2
        for (int ck = 0; ck < 576; ck += 8) {
            float4 sv0 = *(const float4*)&srow[ck];
            float4 sv1 = *(const float4*)&srow[ck + 4];
            float sarr[8] = {sv0.x, sv0.y, sv0.z, sv0.w,
                             sv1.x, sv1.y, sv1.z, sv1.w};
            #pragma unroll
            for (int u = 0; u < 8; u++) {
                float4 wv = __ldg((const float4*)&wt[(ck + u) * 64]);
                float s = sarr[u];
                acc0 += wv.x * s;
                acc1 += wv.y * s;
                acc2 += wv.z * s;
                acc3 += wv.w * s;
            }
        }

        float4 bv = __ldg((const float4*)&db[o0]);
        size_t obase = (((size_t)b * CO + o0) * Hh + h) * Ww + w0 + p;
        out[obase]                 = acc0 + bv.x;
        out[obase + 1 * Hh * Ww]   = acc1 + bv.y;
        out[obase + 2 * Hh * Ww]   = acc2 + bv.z;
        out[obase + 3 * Hh * Ww]   = acc3 + bv.w;
    }
}

extern "C" void kernel_launch(void* const* d_in, const int* in_sizes, int n_in,
                              void* d_out, int out_size)
{
    const float* x   = (const float*)d_in[0];   // [8,64,128,128]
    const float* ow  = (const float*)d_in[1];   // [1152,1,3,3]
    const float* obv = (const float*)d_in[2];   // [1152]
    const float* dw  = (const float*)d_in[3];   // [64,64,3,3]
    const float* db  = (const float*)d_in[4];   // [64]
    float* out = (float*)d_out;                 // [8,64,128,128]

    cudaFuncSetAttribute(deform_fused_kernel,
                         cudaFuncAttributeMaxDynamicSharedMemorySize, SMEM_BYTES);

    transpose_w_kernel<<<(576 * 64 + 255) / 256, 256>>>(dw);

    dim3 grid(Ww / Pp, Hh, Bq);   // (8, 128, 8) = 8192 CTAs
    deform_fused_kernel<<<grid, 256, SMEM_BYTES>>>(x, ow, obv, db, out);
}

// round 3
// speedup vs baseline: 1.8734x; 1.8734x over previous
#include <cuda_runtime.h>
#include <cuda_bf16.h>

// DeformableConv2d fused kernel v3, sm_103a.
//
// x[8,64,128,128], offset_w[1152,1,3,3], offset_b[1152],
// deform_w[64,64,3,3], deform_b[64] -> out[8,64,128,128] fp32
//
// Key math: softmax outputs dy,dx in (0,1) with integer sample base, so
// bilinear corners live in a fixed 4x4 zero-padded patch around each pixel.
//
// v3 = v2's recompute-exp trick (105KB smem -> 2 CTAs/SM)
//    + v1's smem-staged weight GEMM (LDS both operands, FMA-bound),
//      with weight chunks double-buffered in the RECYCLED sow/patch region.

#define Bq 8
#define Cc 64
#define Hh 128
#define Ww 128
#define CO 64
#define Pp 16           // positions (w) per CTA

#define SROW 18         // samp row stride [ck][p], 8B-aligned LDS.64

// smem layout (floats)
#define SM_SOW   0                       // [64][18][10] {w[9],bias} = 11520
#define SM_PATCH 11520                   // [64][4][20]              = 5120
#define SM_SAMP  (11520+5120)            // samp [576][18]           = 10368
#define SM_RED   (SM_SAMP+10368)        // [8][16]                   = 128
#define SM_INVS  (SM_RED+128)           // [16]                      = 16
#define SM_TOTAL (SM_INVS+16)           // 27152 floats
#define SMEM_BYTES (SM_TOTAL * 4)       // 108,608 B -> 2 CTAs/SM

// phase-5 recycled region (overlays sow+patch, 16640 floats available)
#define WCH0 0          // [64 ckl][68 o] = 4352
#define WCH1 4352       // 4352
#define OBUF 8704       // [64][16] = 1024

__device__ float g_wtT[576 * 64];       // wtT[ck][o] = deform_w[o][ck]

__global__ void transpose_w_kernel(const float* __restrict__ dw)
{
    int i = blockIdx.x * 256 + threadIdx.x;
    if (i < 576 * 64) {
        int ck = i >> 6, o = i & 63;
        g_wtT[i] = dw[o * 576 + ck];
    }
}

__global__ __launch_bounds__(256, 2)
void deform_fused_kernel(const float* __restrict__ x,
                         const float* __restrict__ ow,
                         const float* __restrict__ obv,
                         const float* __restrict__ db,
                         float* __restrict__ out)
{
    extern __shared__ float sm[];
    float* sow   = sm + SM_SOW;
    float* patch = sm + SM_PATCH;
    float* samp  = sm + SM_SAMP;
    float* red   = sm + SM_RED;
    float* invS  = sm + SM_INVS;

    const int t  = threadIdx.x;
    const int w0 = blockIdx.x * Pp;
    const int h  = blockIdx.y;
    const int b  = blockIdx.z;

    // ---- Phase 0: stage offset weights {w[9],bias} rows + x patch ----
    for (int i = t; i < 11520; i += 256) {
        int cj = i / 10, m = i - cj * 10;
        sow[i] = (m < 9) ? __ldg(&ow[cj * 9 + m]) : __ldg(&obv[cj]);
    }
    {
        const float* xb = x + (size_t)b * Cc * Hh * Ww;
        for (int i = t; i < 5120; i += 256) {
            int c   = i / 80;
            int r2  = i - c * 80;
            int r   = r2 / 20;
            int col = r2 - r * 20;
            int gy = h - 1 + r;
            int gx = w0 - 1 + col;
            float v = 0.0f;
            if (gy >= 0 && gy < Hh && gx >= 0 && gx < Ww)
                v = xb[(size_t)c * (Hh * Ww) + gy * Ww + gx];
            patch[i] = v;
        }
    }
    __syncthreads();

    // thread mapping for passes A/B: channel c, 4 positions p0..p0+3
    const int c  = t >> 2;
    const int p0 = (t & 3) * 4;

    // patch rows 0..3, cols p0..p0+6 -> registers (reused in A and B)
    float pv[4][7];
    #pragma unroll
    for (int r = 0; r < 4; r++)
        #pragma unroll
        for (int s = 0; s < 7; s++)
            pv[r][s] = patch[(c * 4 + r) * 20 + p0 + s];

    const float* wc = sow + c * 180;

    // ---- Pass A: conv -> exp -> per-position sums ----
    float sums[4] = {0.f, 0.f, 0.f, 0.f};
    #pragma unroll
    for (int j = 0; j < 18; j++) {
        float2 wA = *(const float2*)(wc + j * 10 + 0);
        float2 wB = *(const float2*)(wc + j * 10 + 2);
        float2 wC = *(const float2*)(wc + j * 10 + 4);
        float2 wD = *(const float2*)(wc + j * 10 + 6);
        float2 wE = *(const float2*)(wc + j * 10 + 8);
        float w9[9] = {wA.x, wA.y, wB.x, wB.y, wC.x, wC.y, wD.x, wD.y, wE.x};
        float bias = wE.y;
        float e[4] = {bias, bias, bias, bias};
        #pragma unroll
        for (int r = 0; r < 3; r++)
            #pragma unroll
            for (int s = 0; s < 3; s++) {
                float wv = w9[r * 3 + s];
                #pragma unroll
                for (int q = 0; q < 4; q++)
                    e[q] += wv * pv[r][s + q];
            }
        #pragma unroll
        for (int q = 0; q < 4; q++)
            sums[q] += __expf(e[q]);
    }
    #pragma unroll
    for (int off = 4; off <= 16; off <<= 1)
        #pragma unroll
        for (int q = 0; q < 4; q++)
            sums[q] += __shfl_xor_sync(0xffffffffu, sums[q], off);
    {
        int lane = t & 31, warp = t >> 5;
        if (lane < 4) {
            #pragma unroll
            for (int q = 0; q < 4; q++)
                red[warp * 16 + lane * 4 + q] = sums[q];
        }
    }
    __syncthreads();
    if (t < 16) {
        float s = 0.f;
        #pragma unroll
        for (int w = 0; w < 8; w++) s += red[w * 16 + t];
        invS[t] = 1.0f / s;
    }
    __syncthreads();

    float4 iv4 = *(const float4*)&invS[p0];
    float iv[4] = {iv4.x, iv4.y, iv4.z, iv4.w};

    // ---- Pass B: recompute conv/exp, bilinear sample -> samp[ck][p] ----
    #pragma unroll
    for (int k = 0; k < 9; k++) {
        const int ky = k / 3, kx = k % 3;
        float ey[4], ex[4];
        #pragma unroll
        for (int half = 0; half < 2; half++) {
            int j = 2 * k + half;
            float2 wA = *(const float2*)(wc + j * 10 + 0);
            float2 wB = *(const float2*)(wc + j * 10 + 2);
            float2 wC = *(const float2*)(wc + j * 10 + 4);
            float2 wD = *(const float2*)(wc + j * 10 + 6);
            float2 wE = *(const float2*)(wc + j * 10 + 8);
            float w9[9] = {wA.x, wA.y, wB.x, wB.y, wC.x, wC.y, wD.x, wD.y, wE.x};
            float bias = wE.y;
            float e[4] = {bias, bias, bias, bias};
            #pragma unroll
            for (int r = 0; r < 3; r++)
                #pragma unroll
                for (int s = 0; s < 3; s++) {
                    float wv = w9[r * 3 + s];
                    #pragma unroll
                    for (int q = 0; q < 4; q++)
                        e[q] += wv * pv[r][s + q];
                }
            #pragma unroll
            for (int q = 0; q < 4; q++) {
                if (half == 0) ey[q] = e[q]; else ex[q] = e[q];
            }
        }
        #pragma unroll
        for (int q = 0; q < 4; q++) {
            float dy = __expf(ey[q]) * iv[q];
            float dx = __expf(ex[q]) * iv[q];
            float a00 = pv[ky][q + kx],     a01 = pv[ky][q + kx + 1];
            float a10 = pv[ky + 1][q + kx], a11 = pv[ky + 1][q + kx + 1];
            float top = a00 + dx * (a01 - a00);
            float bot = a10 + dx * (a11 - a10);
            samp[(c * 9 + k) * SROW + p0 + q] = top + dy * (bot - top);
        }
    }
    __syncthreads();   // pass B done; sow/patch now dead -> recycle

    // ---- Phase 5: out[o][p] = sum_ck wtT[ck][o] * samp[ck][p] ----
    // k-split x2; 4 outputs x 2 positions per thread; weights double-buffered
    // in the recycled sow/patch smem region (one barrier per 64-ck chunk).
    float acc[4][2];
    #pragma unroll
    for (int a = 0; a < 4; a++) { acc[a][0] = 0.f; acc[a][1] = 0.f; }

    const int ks = t >> 7;
    const int r5 = t & 127;
    const int o0 = (r5 & 15) * 4;
    const int p5 = (r5 >> 4) * 2;

    {
        // stage chunk 0
        float* w0b = sm + WCH0;
        #pragma unroll
        for (int i = 0; i < 16; i++) {
            int idx = t + 256 * i;
            int ckl = idx >> 6, o = idx & 63;
            w0b[ckl * 68 + o] = g_wtT[ckl * 64 + o];
        }
        __syncthreads();

        for (int cc = 0; cc < 9; cc++) {
            float* wcur = sm + ((cc & 1) ? WCH1 : WCH0);
            float* wnxt = sm + ((cc & 1) ? WCH0 : WCH1);
            if (cc < 8) {
                const float* gsrc = g_wtT + (cc + 1) * 64 * 64;
                #pragma unroll
                for (int i = 0; i < 16; i++) {
                    int idx = t + 256 * i;
                    int ckl = idx >> 6, o = idx & 63;
                    wnxt[ckl * 68 + o] = gsrc[ckl * 64 + o];
                }
            }
            const int ck0 = cc * 64;
            #pragma unroll 8
            for (int kk = 0; kk < 32; kk++) {
                int ckl = ks * 32 + kk;
                float4 wv = *(const float4*)&wcur[ckl * 68 + o0];
                float2 sv = *(const float2*)&samp[(ck0 + ckl) * SROW + p5];
                acc[0][0] += wv.x * sv.x;  acc[0][1] += wv.x * sv.y;
                acc[1][0] += wv.y * sv.x;  acc[1][1] += wv.y * sv.y;
                acc[2][0] += wv.z * sv.x;  acc[2][1] += wv.z * sv.y;
                acc[3][0] += wv.w * sv.x;  acc[3][1] += wv.w * sv.y;
            }
            __syncthreads();
        }
    }

    // ---- combine k-split halves, add bias, store ----
    {
        float* obuf = sm + OBUF;       // [64][16]
        if (ks == 1) {
            #pragma unroll
            for (int oo = 0; oo < 4; oo++)
                #pragma unroll
                for (int pp = 0; pp < 2; pp++)
                    obuf[(o0 + oo) * 16 + p5 + pp] = acc[oo][pp];
        }
        __syncthreads();
        if (ks == 0) {
            #pragma unroll
            for (int oo = 0; oo < 4; oo++) {
                int o = o0 + oo;
                float bias = __ldg(&db[o]);
                #pragma unroll
                for (int pp = 0; pp < 2; pp++) {
                    float v = acc[oo][pp] + obuf[o * 16 + p5 + pp] + bias;
                    out[(((size_t)b * CO + o) * Hh + h) * Ww + w0 + p5 + pp] = v;
                }
            }
        }
    }
}

extern "C" void kernel_launch(void* const* d_in, const int* in_sizes, int n_in,
                              void* d_out, int out_size)
{
    const float* x   = (const float*)d_in[0];   // [8,64,128,128]
    const float* ow  = (const float*)d_in[1];   // [1152,1,3,3]
    const float* obv = (const float*)d_in[2];   // [1152]
    const float* dw  = (const float*)d_in[3];   // [64,64,3,3]
    const float* db  = (const float*)d_in[4];   // [64]
    float* out = (float*)d_out;                 // [8,64,128,128]

    cudaFuncSetAttribute(deform_fused_kernel,
                         cudaFuncAttributeMaxDynamicSharedMemorySize, SMEM_BYTES);

    transpose_w_kernel<<<(576 * 64 + 255) / 256, 256>>>(dw);

    dim3 grid(Ww / Pp, Hh, Bq);   // (8, 128, 8) = 8192 CTAs
    deform_fused_kernel<<<grid, 256, SMEM_BYTES>>>(x, ow, obv, db, out);
}

// round 4
// speedup vs baseline: 1.8785x; 1.0027x over previous
#include <cuda_runtime.h>
#include <cuda_bf16.h>

// DeformableConv2d fused kernel v3, sm_103a.
//
// x[8,64,128,128], offset_w[1152,1,3,3], offset_b[1152],
// deform_w[64,64,3,3], deform_b[64] -> out[8,64,128,128] fp32
//
// Key math: softmax outputs dy,dx in (0,1) with integer sample base, so
// bilinear corners live in a fixed 4x4 zero-padded patch around each pixel.
//
// v3 = v2's recompute-exp trick (105KB smem -> 2 CTAs/SM)
//    + v1's smem-staged weight GEMM (LDS both operands, FMA-bound),
//      with weight chunks double-buffered in the RECYCLED sow/patch region.

#define Bq 8
#define Cc 64
#define Hh 128
#define Ww 128
#define CO 64
#define Pp 16           // positions (w) per CTA

#define SROW 18         // samp row stride [ck][p], 8B-aligned LDS.64

// smem layout (floats)
#define SM_SOW   0                       // [64][18][10] {w[9],bias} = 11520
#define SM_PATCH 11520                   // [64][4][20]              = 5120
#define SM_SAMP  (11520+5120)            // samp [576][18]           = 10368
#define SM_RED   (SM_SAMP+10368)        // [8][16]                   = 128
#define SM_INVS  (SM_RED+128)           // [16]                      = 16
#define SM_TOTAL (SM_INVS+16)           // 27152 floats
#define SMEM_BYTES (SM_TOTAL * 4)       // 108,608 B -> 2 CTAs/SM

// phase-5 recycled region (overlays sow+patch, 16640 floats available)
#define WCH0 0          // [64 ckl][68 o] = 4352
#define WCH1 4352       // 4352
#define OBUF 8704       // [64][16] = 1024

__device__ float g_wtT[576 * 64];       // wtT[ck][o] = deform_w[o][ck]

__global__ void transpose_w_kernel(const float* __restrict__ dw)
{
    int i = blockIdx.x * 256 + threadIdx.x;
    if (i < 576 * 64) {
        int ck = i >> 6, o = i & 63;
        g_wtT[i] = dw[o * 576 + ck];
    }
}

__global__ __launch_bounds__(256, 2)
void deform_fused_kernel(const float* __restrict__ x,
                         const float* __restrict__ ow,
                         const float* __restrict__ obv,
                         const float* __restrict__ db,
                         float* __restrict__ out)
{
    extern __shared__ float sm[];
    float* sow   = sm + SM_SOW;
    float* patch = sm + SM_PATCH;
    float* samp  = sm + SM_SAMP;
    float* red   = sm + SM_RED;
    float* invS  = sm + SM_INVS;

    const int t  = threadIdx.x;
    const int w0 = blockIdx.x * Pp;
    const int h  = blockIdx.y;
    const int b  = blockIdx.z;

    // ---- Phase 0: stage offset weights {w[9],bias} rows + x patch ----
    for (int i = t; i < 11520; i += 256) {
        int cj = i / 10, m = i - cj * 10;
        sow[i] = (m < 9) ? __ldg(&ow[cj * 9 + m]) : __ldg(&obv[cj]);
    }
    {
        const float* xb = x + (size_t)b * Cc * Hh * Ww;
        for (int i = t; i < 5120; i += 256) {
            int c   = i / 80;
            int r2  = i - c * 80;
            int r   = r2 / 20;
            int col = r2 - r * 20;
            int gy = h - 1 + r;
            int gx = w0 - 1 + col;
            float v = 0.0f;
            if (gy >= 0 && gy < Hh && gx >= 0 && gx < Ww)
                v = xb[(size_t)c * (Hh * Ww) + gy * Ww + gx];
            patch[i] = v;
        }
    }
    __syncthreads();

    // thread mapping for passes A/B: channel c, 4 positions p0..p0+3
    const int c  = t >> 2;
    const int p0 = (t & 3) * 4;

    // patch rows 0..3, cols p0..p0+6 -> registers (reused in A and B)
    float pv[4][7];
    #pragma unroll
    for (int r = 0; r < 4; r++)
        #pragma unroll
        for (int s = 0; s < 7; s++)
            pv[r][s] = patch[(c * 4 + r) * 20 + p0 + s];

    const float* wc = sow + c * 180;

    // ---- Pass A: conv -> exp -> per-position sums ----
    float sums[4] = {0.f, 0.f, 0.f, 0.f};
    #pragma unroll
    for (int j = 0; j < 18; j++) {
        float2 wA = *(const float2*)(wc + j * 10 + 0);
        float2 wB = *(const float2*)(wc + j * 10 + 2);
        float2 wC = *(const float2*)(wc + j * 10 + 4);
        float2 wD = *(const float2*)(wc + j * 10 + 6);
        float2 wE = *(const float2*)(wc + j * 10 + 8);
        float w9[9] = {wA.x, wA.y, wB.x, wB.y, wC.x, wC.y, wD.x, wD.y, wE.x};
        float bias = wE.y;
        float e[4] = {bias, bias, bias, bias};
        #pragma unroll
        for (int r = 0; r < 3; r++)
            #pragma unroll
            for (int s = 0; s < 3; s++) {
                float wv = w9[r * 3 + s];
                #pragma unroll
                for (int q = 0; q < 4; q++)
                    e[q] += wv * pv[r][s + q];
            }
        #pragma unroll
        for (int q = 0; q < 4; q++)
            sums[q] += __expf(e[q]);
    }
    #pragma unroll
    for (int off = 4; off <= 16; off <<= 1)
        #pragma unroll
        for (int q = 0; q < 4; q++)
            sums[q] += __shfl_xor_sync(0xffffffffu, sums[q], off);
    {
        int lane = t & 31, warp = t >> 5;
        if (lane < 4) {
            #pragma unroll
            for (int q = 0; q < 4; q++)
                red[warp * 16 + lane * 4 + q] = sums[q];
        }
    }
    __syncthreads();
    if (t < 16) {
        float s = 0.f;
        #pragma unroll
        for (int w = 0; w < 8; w++) s += red[w * 16 + t];
        invS[t] = 1.0f / s;
    }
    __syncthreads();

    float4 iv4 = *(const float4*)&invS[p0];
    float iv[4] = {iv4.x, iv4.y, iv4.z, iv4.w};

    // ---- Pass B: recompute conv/exp, bilinear sample -> samp[ck][p] ----
    #pragma unroll
    for (int k = 0; k < 9; k++) {
        const int ky = k / 3, kx = k % 3;
        float ey[4], ex[4];
        #pragma unroll
        for (int half = 0; half < 2; half++) {
            int j = 2 * k + half;
            float2 wA = *(const float2*)(wc + j * 10 + 0);
            float2 wB = *(const float2*)(wc + j * 10 + 2);
            float2 wC = *(const float2*)(wc + j * 10 + 4);
            float2 wD = *(const float2*)(wc + j * 10 + 6);
            float2 wE = *(const float2*)(wc + j * 10 + 8);
            float w9[9] = {wA.x, wA.y, wB.x, wB.y, wC.x, wC.y, wD.x, wD.y, wE.x};
            float bias = wE.y;
            float e[4] = {bias, bias, bias, bias};
            #pragma unroll
            for (int r = 0; r < 3; r++)
                #pragma unroll
                for (int s = 0; s < 3; s++) {
                    float wv = w9[r * 3 + s];
                    #pragma unroll
                    for (int q = 0; q < 4; q++)
                        e[q] += wv * pv[r][s + q];
                }
            #pragma unroll
            for (int q = 0; q < 4; q++) {
                if (half == 0) ey[q] = e[q]; else ex[q] = e[q];
            }
        }
        #pragma unroll
        for (int q = 0; q < 4; q++) {
            float dy = __expf(ey[q]) * iv[q];
            float dx = __expf(ex[q]) * iv[q];
            float a00 = pv[ky][q + kx],     a01 = pv[ky][q + kx + 1];
            float a10 = pv[ky + 1][q + kx], a11 = pv[ky + 1][q + kx + 1];
            float top = a00 + dx * (a01 - a00);
            float bot = a10 + dx * (a11 - a10);
            samp[(c * 9 + k) * SROW + p0 + q] = top + dy * (bot - top);
        }
    }
    __syncthreads();   // pass B done; sow/patch now dead -> recycle

    // ---- Phase 5: out[o][p] = sum_ck wtT[ck][o] * samp[ck][p] ----
    // k-split x2; 4 outputs x 2 positions per thread; weights double-buffered
    // in the recycled sow/patch smem region (one barrier per 64-ck chunk).
    float acc[4][2];
    #pragma unroll
    for (int a = 0; a < 4; a++) { acc[a][0] = 0.f; acc[a][1] = 0.f; }

    const int ks = t >> 7;
    const int r5 = t & 127;
    const int o0 = (r5 & 15) * 4;
    const int p5 = (r5 >> 4) * 2;

    {
        // stage chunk 0
        float* w0b = sm + WCH0;
        #pragma unroll
        for (int i = 0; i < 16; i++) {
            int idx = t + 256 * i;
            int ckl = idx >> 6, o = idx & 63;
            w0b[ckl * 68 + o] = g_wtT[ckl * 64 + o];
        }
        __syncthreads();

        for (int cc = 0; cc < 9; cc++) {
            float* wcur = sm + ((cc & 1) ? WCH1 : WCH0);
            float* wnxt = sm + ((cc & 1) ? WCH0 : WCH1);
            if (cc < 8) {
                const float* gsrc = g_wtT + (cc + 1) * 64 * 64;
                #pragma unroll
                for (int i = 0; i < 16; i++) {
                    int idx = t + 256 * i;
                    int ckl = idx >> 6, o = idx & 63;
                    wnxt[ckl * 68 + o] = gsrc[ckl * 64 + o];
                }
            }
            const int ck0 = cc * 64;
            #pragma unroll 8
            for (int kk = 0; kk < 32; kk++) {
                int ckl = ks * 32 + kk;
                float4 wv = *(const float4*)&wcur[ckl * 68 + o0];
                float2 sv = *(const float2*)&samp[(ck0 + ckl) * SROW + p5];
                acc[0][0] += wv.x * sv.x;  acc[0][1] += wv.x * sv.y;
                acc[1][0] += wv.y * sv.x;  acc[1][1] += wv.y * sv.y;
                acc[2][0] += wv.z * sv.x;  acc[2][1] += wv.z * sv.y;
                acc[3][0] += wv.w * sv.x;  acc[3][1] += wv.w * sv.y;
            }
            __syncthreads();
        }
    }

    // ---- combine k-split halves, add bias, store ----
    {
        float* obuf = sm + OBUF;       // [64][16]
        if (ks == 1) {
            #pragma unroll
            for (int oo = 0; oo < 4; oo++)
                #pragma unroll
                for (int pp = 0; pp < 2; pp++)
                    obuf[(o0 + oo) * 16 + p5 + pp] = acc[oo][pp];
        }
        __syncthreads();
        if (ks == 0) {
            #pragma unroll
            for (int oo = 0; oo < 4; oo++) {
                int o = o0 + oo;
                float bias = __ldg(&db[o]);
                #pragma unroll
                for (int pp = 0; pp < 2; pp++) {
                    float v = acc[oo][pp] + obuf[o * 16 + p5 + pp] + bias;
                    out[(((size_t)b * CO + o) * Hh + h) * Ww + w0 + p5 + pp] = v;
                }
            }
        }
    }
}

extern "C" void kernel_launch(void* const* d_in, const int* in_sizes, int n_in,
                              void* d_out, int out_size)
{
    const float* x   = (const float*)d_in[0];   // [8,64,128,128]
    const float* ow  = (const float*)d_in[1];   // [1152,1,3,3]
    const float* obv = (const float*)d_in[2];   // [1152]
    const float* dw  = (const float*)d_in[3];   // [64,64,3,3]
    const float* db  = (const float*)d_in[4];   // [64]
    float* out = (float*)d_out;                 // [8,64,128,128]

    cudaFuncSetAttribute(deform_fused_kernel,
                         cudaFuncAttributeMaxDynamicSharedMemorySize, SMEM_BYTES);

    transpose_w_kernel<<<(576 * 64 + 255) / 256, 256>>>(dw);

    dim3 grid(Ww / Pp, Hh, Bq);   // (8, 128, 8) = 8192 CTAs
    deform_fused_kernel<<<grid, 256, SMEM_BYTES>>>(x, ow, obv, db, out);
}

// round 5
// speedup vs baseline: 1.9472x; 1.0366x over previous
#include <cuda_runtime.h>
#include <cuda_bf16.h>

// DeformableConv2d fused kernel v4, sm_103a.
//
// x[8,64,128,128], offset_w[1152,1,3,3], offset_b[1152],
// deform_w[64,64,3,3], deform_b[64] -> out[8,64,128,128] fp32
//
// v4 vs v3 (766us): offset weights moved out of per-CTA smem into a
// preprocessed __device__ global (they are CTA-invariant) -> smem 108.6KB
// -> 62.5KB -> 3 CTAs/SM. Phase-5 weight double-buffer shrunk to 32-ck
// chunks so it fits the recycled patch region.

#define Bq 8
#define Cc 64
#define Hh 128
#define Ww 128
#define CO 64
#define Pp 16           // positions (w) per CTA

#define SROW 18         // samp row stride [ck][p], 8B-aligned LDS.64

// smem layout (floats)
#define SM_PATCH 0                      // [64][4][20] = 5120 (recycled in ph5)
#define SM_SAMP  5120                   // samp [576][18] = 10368
#define SM_RED   (SM_SAMP+10368)        // [8][16] = 128
#define SM_INVS  (SM_RED+128)           // [16]
#define SM_TOTAL (SM_INVS+16)           // 15632 floats
#define SMEM_BYTES (SM_TOTAL * 4)       // 62,528 B -> 3 CTAs/SM

// phase-5 recycled region overlaying patch (5120 floats available)
#define WCH0 0          // [32 ckl][68 o] = 2176
#define WCH1 2176       // 2176  (total 4352 <= 5120)
// obuf reuses WCH0 after the final mainloop barrier

__device__ float g_wtT[576 * 64];       // wtT[ck][o] = deform_w[o][ck]
__device__ float g_sow[64 * 18 * 10];   // per (c,j): {w[9], bias}

__global__ void prep_kernel(const float* __restrict__ dw,
                            const float* __restrict__ ow,
                            const float* __restrict__ obv)
{
    int i = blockIdx.x * 256 + threadIdx.x;
    if (i < 576 * 64) {
        int ck = i >> 6, o = i & 63;
        g_wtT[i] = dw[o * 576 + ck];
    }
    if (i < 11520) {
        int cj = i / 10, m = i - cj * 10;
        g_sow[i] = (m < 9) ? ow[cj * 9 + m] : obv[cj];
    }
}

__device__ __forceinline__ void load_w9(const float* wc, int j,
                                        float w9[9], float& bias)
{
    float2 wA = __ldg((const float2*)(wc + j * 10 + 0));
    float2 wB = __ldg((const float2*)(wc + j * 10 + 2));
    float2 wC = __ldg((const float2*)(wc + j * 10 + 4));
    float2 wD = __ldg((const float2*)(wc + j * 10 + 6));
    float2 wE = __ldg((const float2*)(wc + j * 10 + 8));
    w9[0] = wA.x; w9[1] = wA.y; w9[2] = wB.x; w9[3] = wB.y;
    w9[4] = wC.x; w9[5] = wC.y; w9[6] = wD.x; w9[7] = wD.y; w9[8] = wE.x;
    bias = wE.y;
}

__global__ __launch_bounds__(256, 3)
void deform_fused_kernel(const float* __restrict__ x,
                         const float* __restrict__ db,
                         float* __restrict__ out)
{
    extern __shared__ float sm[];
    float* patch = sm + SM_PATCH;
    float* samp  = sm + SM_SAMP;
    float* red   = sm + SM_RED;
    float* invS  = sm + SM_INVS;

    const int t  = threadIdx.x;
    const int w0 = blockIdx.x * Pp;
    const int h  = blockIdx.y;
    const int b  = blockIdx.z;

    // ---- Phase 1: load 4x20 zero-padded x patch per channel ----
    {
        const float* xb = x + (size_t)b * Cc * Hh * Ww;
        for (int i = t; i < 5120; i += 256) {
            int c   = i / 80;
            int r2  = i - c * 80;
            int r   = r2 / 20;
            int col = r2 - r * 20;
            int gy = h - 1 + r;
            int gx = w0 - 1 + col;
            float v = 0.0f;
            if (gy >= 0 && gy < Hh && gx >= 0 && gx < Ww)
                v = xb[(size_t)c * (Hh * Ww) + gy * Ww + gx];
            patch[i] = v;
        }
    }
    __syncthreads();

    // thread mapping for passes A/B: channel c, 4 positions p0..p0+3
    const int c  = t >> 2;
    const int p0 = (t & 3) * 4;
    const float* wc = g_sow + c * 180;

    // ---- Pass A: conv -> exp -> per-position sums (rows 0..2, cols 0..5) ----
    float sums[4] = {0.f, 0.f, 0.f, 0.f};
    {
        float pv3[3][6];
        #pragma unroll
        for (int r = 0; r < 3; r++)
            #pragma unroll
            for (int s = 0; s < 6; s++)
                pv3[r][s] = patch[(c * 4 + r) * 20 + p0 + s];

        #pragma unroll
        for (int j = 0; j < 18; j++) {
            float w9[9], bias;
            load_w9(wc, j, w9, bias);
            float e[4] = {bias, bias, bias, bias};
            #pragma unroll
            for (int r = 0; r < 3; r++)
                #pragma unroll
                for (int s = 0; s < 3; s++) {
                    float wv = w9[r * 3 + s];
                    #pragma unroll
                    for (int q = 0; q < 4; q++)
                        e[q] += wv * pv3[r][s + q];
                }
            #pragma unroll
            for (int q = 0; q < 4; q++)
                sums[q] += __expf(e[q]);
        }
    }
    #pragma unroll
    for (int off = 4; off <= 16; off <<= 1)
        #pragma unroll
        for (int q = 0; q < 4; q++)
            sums[q] += __shfl_xor_sync(0xffffffffu, sums[q], off);
    {
        int lane = t & 31, warp = t >> 5;
        if (lane < 4) {
            #pragma unroll
            for (int q = 0; q < 4; q++)
                red[warp * 16 + lane * 4 + q] = sums[q];
        }
    }
    __syncthreads();
    if (t < 16) {
        float s = 0.f;
        #pragma unroll
        for (int w = 0; w < 8; w++) s += red[w * 16 + t];
        invS[t] = 1.0f / s;
    }
    __syncthreads();

    float4 iv4 = *(const float4*)&invS[p0];
    float iv[4] = {iv4.x, iv4.y, iv4.z, iv4.w};

    // ---- Pass B: recompute conv/exp, bilinear sample -> samp[ck][p] ----
    {
        float pv[4][7];
        #pragma unroll
        for (int r = 0; r < 4; r++)
            #pragma unroll
            for (int s = 0; s < 7; s++)
                pv[r][s] = patch[(c * 4 + r) * 20 + p0 + s];

        #pragma unroll
        for (int k = 0; k < 9; k++) {
            const int ky = k / 3, kx = k % 3;
            float ey[4], ex[4];
            #pragma unroll
            for (int half = 0; half < 2; half++) {
                float w9[9], bias;
                load_w9(wc, 2 * k + half, w9, bias);
                float e[4] = {bias, bias, bias, bias};
                #pragma unroll
                for (int r = 0; r < 3; r++)
                    #pragma unroll
                    for (int s = 0; s < 3; s++) {
                        float wv = w9[r * 3 + s];
                        #pragma unroll
                        for (int q = 0; q < 4; q++)
                            e[q] += wv * pv[r][s + q];
                    }
                #pragma unroll
                for (int q = 0; q < 4; q++) {
                    if (half == 0) ey[q] = e[q]; else ex[q] = e[q];
                }
            }
            #pragma unroll
            for (int q = 0; q < 4; q++) {
                float dy = __expf(ey[q]) * iv[q];
                float dx = __expf(ex[q]) * iv[q];
                float a00 = pv[ky][q + kx],     a01 = pv[ky][q + kx + 1];
                float a10 = pv[ky + 1][q + kx], a11 = pv[ky + 1][q + kx + 1];
                float top = a00 + dx * (a01 - a00);
                float bot = a10 + dx * (a11 - a10);
                samp[(c * 9 + k) * SROW + p0 + q] = top + dy * (bot - top);
            }
        }
    }
    __syncthreads();   // pass B done; patch now dead -> recycle for weights

    // ---- Phase 5: out[o][p] = sum_ck wtT[ck][o] * samp[ck][p] ----
    // k-split x2 over 32-ck double-buffered weight chunks in recycled patch.
    float acc[4][2];
    #pragma unroll
    for (int a = 0; a < 4; a++) { acc[a][0] = 0.f; acc[a][1] = 0.f; }

    const int ks = t >> 7;
    const int r5 = t & 127;
    const int o0 = (r5 & 15) * 4;
    const int p5 = (r5 >> 4) * 2;

    {
        // stage chunk 0 (32 ckl x 64 o = 2048 floats, 8 per thread)
        float* wbuf = sm + WCH0;
        #pragma unroll
        for (int i = 0; i < 8; i++) {
            int idx = t + 256 * i;
            int ckl = idx >> 6, o = idx & 63;
            wbuf[ckl * 68 + o] = g_wtT[idx];
        }
        __syncthreads();

        for (int cc = 0; cc < 18; cc++) {
            float* wcur = sm + ((cc & 1) ? WCH1 : WCH0);
            float* wnxt = sm + ((cc & 1) ? WCH0 : WCH1);
            if (cc < 17) {
                const float* gsrc = g_wtT + (cc + 1) * 2048;
                #pragma unroll
                for (int i = 0; i < 8; i++) {
                    int idx = t + 256 * i;
                    int ckl = idx >> 6, o = idx & 63;
                    wnxt[ckl * 68 + o] = gsrc[idx];
                }
            }
            const int ck0 = cc * 32;
            #pragma unroll
            for (int kk = 0; kk < 16; kk++) {
                int ckl = ks * 16 + kk;
                float4 wv = *(const float4*)&wcur[ckl * 68 + o0];
                float2 sv = *(const float2*)&samp[(ck0 + ckl) * SROW + p5];
                acc[0][0] += wv.x * sv.x;  acc[0][1] += wv.x * sv.y;
                acc[1][0] += wv.y * sv.x;  acc[1][1] += wv.y * sv.y;
                acc[2][0] += wv.z * sv.x;  acc[2][1] += wv.z * sv.y;
                acc[3][0] += wv.w * sv.x;  acc[3][1] += wv.w * sv.y;
            }
            __syncthreads();
        }
    }

    // ---- combine k-split halves, add bias, store ----
    {
        float* obuf = sm + WCH0;       // [64][16], recycled again
        if (ks == 1) {
            #pragma unroll
            for (int oo = 0; oo < 4; oo++)
                #pragma unroll
                for (int pp = 0; pp < 2; pp++)
                    obuf[(o0 + oo) * 16 + p5 + pp] = acc[oo][pp];
        }
        __syncthreads();
        if (ks == 0) {
            #pragma unroll
            for (int oo = 0; oo < 4; oo++) {
                int o = o0 + oo;
                float bias = __ldg(&db[o]);
                #pragma unroll
                for (int pp = 0; pp < 2; pp++) {
                    float v = acc[oo][pp] + obuf[o * 16 + p5 + pp] + bias;
                    out[(((size_t)b * CO + o) * Hh + h) * Ww + w0 + p5 + pp] = v;
                }
            }
        }
    }
}

extern "C" void kernel_launch(void* const* d_in, const int* in_sizes, int n_in,
                              void* d_out, int out_size)
{
    const float* x   = (const float*)d_in[0];   // [8,64,128,128]
    const float* ow  = (const float*)d_in[1];   // [1152,1,3,3]
    const float* obv = (const float*)d_in[2];   // [1152]
    const float* dw  = (const float*)d_in[3];   // [64,64,3,3]
    const float* db  = (const float*)d_in[4];   // [64]
    float* out = (float*)d_out;                 // [8,64,128,128]

    cudaFuncSetAttribute(deform_fused_kernel,
                         cudaFuncAttributeMaxDynamicSharedMemorySize, SMEM_BYTES);

    prep_kernel<<<(576 * 64 + 255) / 256, 256>>>(dw, ow, obv);

    dim3 grid(Ww / Pp, Hh, Bq);   // (8, 128, 8) = 8192 CTAs
    deform_fused_kernel<<<grid, 256, SMEM_BYTES>>>(x, db, out);
}

// round 6
// speedup vs baseline: 2.3872x; 1.2259x over previous
#include <cuda_runtime.h>
#include <cuda_bf16.h>

// DeformableConv2d fused kernel v5, sm_103a.
//
// x[8,64,128,128], offset_w[1152,1,3,3], offset_b[1152],
// deform_w[64,64,3,3], deform_b[64] -> out[8,64,128,128] fp32
//
// v5 vs v4 (739us): GEMM register blocking 4o x 4p (k-split 4), 2 B of smem
// per FMA (was 3) -> shared-crossbar demand meets the FFMA floor. samp row
// stride 20 for float4-aligned loads. Final store is STG.128.

#define Bq 8
#define Cc 64
#define Hh 128
#define Ww 128
#define CO 64
#define Pp 16           // positions (w) per CTA

#define SROW 20         // samp row stride [ck][p], 16B-aligned float4 loads

// smem layout (floats)
#define SM_PATCH 0                      // [64][4][20] = 5120 (recycled in ph5)
#define SM_SAMP  5120                   // samp [576][20] = 11520
#define SM_RED   (SM_SAMP+11520)        // [8][16] = 128
#define SM_INVS  (SM_RED+128)           // [16]
#define SM_TOTAL (SM_INVS+16)           // 16784 floats
#define SMEM_BYTES (SM_TOTAL * 4)       // 67,136 B -> 3 CTAs/SM

// phase-5 recycled region overlaying patch (5120 floats available)
#define WCH0 0          // [32 ckl][68 o] = 2176
#define WCH1 2176       // 2176  (total 4352 <= 5120)
// obuf (3 x 1024) overlays WCH0 after the final mainloop barrier

__device__ float g_wtT[576 * 64];       // wtT[ck][o] = deform_w[o][ck]
__device__ float g_sow[64 * 18 * 10];   // per (c,j): {w[9], bias}

__global__ void prep_kernel(const float* __restrict__ dw,
                            const float* __restrict__ ow,
                            const float* __restrict__ obv)
{
    int i = blockIdx.x * 256 + threadIdx.x;
    if (i < 576 * 64) {
        int ck = i >> 6, o = i & 63;
        g_wtT[i] = dw[o * 576 + ck];
    }
    if (i < 11520) {
        int cj = i / 10, m = i - cj * 10;
        g_sow[i] = (m < 9) ? ow[cj * 9 + m] : obv[cj];
    }
}

__device__ __forceinline__ void load_w9(const float* wc, int j,
                                        float w9[9], float& bias)
{
    float2 wA = __ldg((const float2*)(wc + j * 10 + 0));
    float2 wB = __ldg((const float2*)(wc + j * 10 + 2));
    float2 wC = __ldg((const float2*)(wc + j * 10 + 4));
    float2 wD = __ldg((const float2*)(wc + j * 10 + 6));
    float2 wE = __ldg((const float2*)(wc + j * 10 + 8));
    w9[0] = wA.x; w9[1] = wA.y; w9[2] = wB.x; w9[3] = wB.y;
    w9[4] = wC.x; w9[5] = wC.y; w9[6] = wD.x; w9[7] = wD.y; w9[8] = wE.x;
    bias = wE.y;
}

__global__ __launch_bounds__(256, 3)
void deform_fused_kernel(const float* __restrict__ x,
                         const float* __restrict__ db,
                         float* __restrict__ out)
{
    extern __shared__ float sm[];
    float* patch = sm + SM_PATCH;
    float* samp  = sm + SM_SAMP;
    float* red   = sm + SM_RED;
    float* invS  = sm + SM_INVS;

    const int t  = threadIdx.x;
    const int w0 = blockIdx.x * Pp;
    const int h  = blockIdx.y;
    const int b  = blockIdx.z;

    // ---- Phase 1: load 4x20 zero-padded x patch per channel ----
    {
        const float* xb = x + (size_t)b * Cc * Hh * Ww;
        for (int i = t; i < 5120; i += 256) {
            int c   = i / 80;
            int r2  = i - c * 80;
            int r   = r2 / 20;
            int col = r2 - r * 20;
            int gy = h - 1 + r;
            int gx = w0 - 1 + col;
            float v = 0.0f;
            if (gy >= 0 && gy < Hh && gx >= 0 && gx < Ww)
                v = xb[(size_t)c * (Hh * Ww) + gy * Ww + gx];
            patch[i] = v;
        }
    }
    __syncthreads();

    // thread mapping for passes A/B: channel c, 4 positions p0..p0+3
    const int c  = t >> 2;
    const int pA = (t & 3) * 4;
    const float* wc = g_sow + c * 180;

    // ---- Pass A: conv -> exp -> per-position sums ----
    float sums[4] = {0.f, 0.f, 0.f, 0.f};
    {
        float pv3[3][6];
        #pragma unroll
        for (int r = 0; r < 3; r++)
            #pragma unroll
            for (int s = 0; s < 6; s++)
                pv3[r][s] = patch[(c * 4 + r) * 20 + pA + s];

        #pragma unroll
        for (int j = 0; j < 18; j++) {
            float w9[9], bias;
            load_w9(wc, j, w9, bias);
            float e[4] = {bias, bias, bias, bias};
            #pragma unroll
            for (int r = 0; r < 3; r++)
                #pragma unroll
                for (int s = 0; s < 3; s++) {
                    float wv = w9[r * 3 + s];
                    #pragma unroll
                    for (int q = 0; q < 4; q++)
                        e[q] += wv * pv3[r][s + q];
                }
            #pragma unroll
            for (int q = 0; q < 4; q++)
                sums[q] += __expf(e[q]);
        }
    }
    #pragma unroll
    for (int off = 4; off <= 16; off <<= 1)
        #pragma unroll
        for (int q = 0; q < 4; q++)
            sums[q] += __shfl_xor_sync(0xffffffffu, sums[q], off);
    {
        int lane = t & 31, warp = t >> 5;
        if (lane < 4) {
            #pragma unroll
            for (int q = 0; q < 4; q++)
                red[warp * 16 + lane * 4 + q] = sums[q];
        }
    }
    __syncthreads();
    if (t < 16) {
        float s = 0.f;
        #pragma unroll
        for (int w = 0; w < 8; w++) s += red[w * 16 + t];
        invS[t] = 1.0f / s;
    }
    __syncthreads();

    float4 iv4 = *(const float4*)&invS[pA];
    float iv[4] = {iv4.x, iv4.y, iv4.z, iv4.w};

    // ---- Pass B: recompute conv/exp, bilinear sample -> samp[ck][p] ----
    {
        float pv[4][7];
        #pragma unroll
        for (int r = 0; r < 4; r++)
            #pragma unroll
            for (int s = 0; s < 7; s++)
                pv[r][s] = patch[(c * 4 + r) * 20 + pA + s];

        #pragma unroll
        for (int k = 0; k < 9; k++) {
            const int ky = k / 3, kx = k % 3;
            float ey[4], ex[4];
            #pragma unroll
            for (int half = 0; half < 2; half++) {
                float w9[9], bias;
                load_w9(wc, 2 * k + half, w9, bias);
                float e[4] = {bias, bias, bias, bias};
                #pragma unroll
                for (int r = 0; r < 3; r++)
                    #pragma unroll
                    for (int s = 0; s < 3; s++) {
                        float wv = w9[r * 3 + s];
                        #pragma unroll
                        for (int q = 0; q < 4; q++)
                            e[q] += wv * pv[r][s + q];
                    }
                #pragma unroll
                for (int q = 0; q < 4; q++) {
                    if (half == 0) ey[q] = e[q]; else ex[q] = e[q];
                }
            }
            float res[4];
            #pragma unroll
            for (int q = 0; q < 4; q++) {
                float dy = __expf(ey[q]) * iv[q];
                float dx = __expf(ex[q]) * iv[q];
                float a00 = pv[ky][q + kx],     a01 = pv[ky][q + kx + 1];
                float a10 = pv[ky + 1][q + kx], a11 = pv[ky + 1][q + kx + 1];
                float top = a00 + dx * (a01 - a00);
                float bot = a10 + dx * (a11 - a10);
                res[q] = top + dy * (bot - top);
            }
            *(float4*)&samp[(c * 9 + k) * SROW + pA] =
                make_float4(res[0], res[1], res[2], res[3]);
        }
    }
    __syncthreads();   // pass B done; patch now dead -> recycle for weights

    // ---- Phase 5: out[o][p] = sum_ck wtT[ck][o] * samp[ck][p] ----
    // 4o x 4p register block, k-split 4; 32-ck double-buffered weight chunks.
    float acc[4][4];
    #pragma unroll
    for (int a = 0; a < 4; a++)
        #pragma unroll
        for (int p = 0; p < 4; p++) acc[a][p] = 0.f;

    const int ks = t >> 6;            // k-slice 0..3
    const int o0 = ((t >> 2) & 15) * 4;
    const int p0 = (t & 3) * 4;

    {
        // stage chunk 0 (32 ckl x 64 o = 2048 floats, 8 per thread)
        float* wbuf = sm + WCH0;
        #pragma unroll
        for (int i = 0; i < 8; i++) {
            int idx = t + 256 * i;
            int ckl = idx >> 6, o = idx & 63;
            wbuf[ckl * 68 + o] = g_wtT[idx];
        }
        __syncthreads();

        for (int cc = 0; cc < 18; cc++) {
            float* wcur = sm + ((cc & 1) ? WCH1 : WCH0);
            float* wnxt = sm + ((cc & 1) ? WCH0 : WCH1);
            if (cc < 17) {
                const float* gsrc = g_wtT + (cc + 1) * 2048;
                #pragma unroll
                for (int i = 0; i < 8; i++) {
                    int idx = t + 256 * i;
                    int ckl = idx >> 6, o = idx & 63;
                    wnxt[ckl * 68 + o] = gsrc[idx];
                }
            }
            const int ck0 = cc * 32;
            #pragma unroll
            for (int kk = 0; kk < 8; kk++) {
                int ckl = ks * 8 + kk;
                float4 wv = *(const float4*)&wcur[ckl * 68 + o0];
                float4 sv = *(const float4*)&samp[(ck0 + ckl) * SROW + p0];
                acc[0][0] += wv.x * sv.x; acc[0][1] += wv.x * sv.y;
                acc[0][2] += wv.x * sv.z; acc[0][3] += wv.x * sv.w;
                acc[1][0] += wv.y * sv.x; acc[1][1] += wv.y * sv.y;
                acc[1][2] += wv.y * sv.z; acc[1][3] += wv.y * sv.w;
                acc[2][0] += wv.z * sv.x; acc[2][1] += wv.z * sv.y;
                acc[2][2] += wv.z * sv.z; acc[2][3] += wv.z * sv.w;
                acc[3][0] += wv.w * sv.x; acc[3][1] += wv.w * sv.y;
                acc[3][2] += wv.w * sv.z; acc[3][3] += wv.w * sv.w;
            }
            __syncthreads();
        }
    }

    // ---- combine k-split quarters, add bias, store (STG.128) ----
    {
        float* obuf = sm + WCH0;       // 3 slices x [64][16]
        if (ks > 0) {
            float* os = obuf + (ks - 1) * 1024;
            #pragma unroll
            for (int oo = 0; oo < 4; oo++)
                *(float4*)&os[(o0 + oo) * 16 + p0] =
                    make_float4(acc[oo][0], acc[oo][1], acc[oo][2], acc[oo][3]);
        }
        __syncthreads();
        if (ks == 0) {
            float4 bv = __ldg((const float4*)&db[o0]);
            float bvs[4] = {bv.x, bv.y, bv.z, bv.w};
            #pragma unroll
            for (int oo = 0; oo < 4; oo++) {
                int o = o0 + oo;
                float4 r0 = *(const float4*)&obuf[0 * 1024 + o * 16 + p0];
                float4 r1 = *(const float4*)&obuf[1 * 1024 + o * 16 + p0];
                float4 r2 = *(const float4*)&obuf[2 * 1024 + o * 16 + p0];
                float4 v;
                v.x = acc[oo][0] + r0.x + r1.x + r2.x + bvs[oo];
                v.y = acc[oo][1] + r0.y + r1.y + r2.y + bvs[oo];
                v.z = acc[oo][2] + r0.z + r1.z + r2.z + bvs[oo];
                v.w = acc[oo][3] + r0.w + r1.w + r2.w + bvs[oo];
                *(float4*)&out[(((size_t)b * CO + o) * Hh + h) * Ww + w0 + p0] = v;
            }
        }
    }
}

extern "C" void kernel_launch(void* const* d_in, const int* in_sizes, int n_in,
                              void* d_out, int out_size)
{
    const float* x   = (const float*)d_in[0];   // [8,64,128,128]
    const float* ow  = (const float*)d_in[1];   // [1152,1,3,3]
    const float* obv = (const float*)d_in[2];   // [1152]
    const float* dw  = (const float*)d_in[3];   // [64,64,3,3]
    const float* db  = (const float*)d_in[4];   // [64]
    float* out = (float*)d_out;                 // [8,64,128,128]

    cudaFuncSetAttribute(deform_fused_kernel,
                         cudaFuncAttributeMaxDynamicSharedMemorySize, SMEM_BYTES);

    prep_kernel<<<(576 * 64 + 255) / 256, 256>>>(dw, ow, obv);

    dim3 grid(Ww / Pp, Hh, Bq);   // (8, 128, 8) = 8192 CTAs
    deform_fused_kernel<<<grid, 256, SMEM_BYTES>>>(x, db, out);
}

// round 8
// speedup vs baseline: 2.7778x; 1.1636x over previous
#include <cuda_runtime.h>
#include <cuda_bf16.h>
#include <cstdint>

// DeformableConv2d fused kernel v6b, sm_103a.  (v6 + missing <cstdint>)
//
// x[8,64,128,128], offset_w[1152,1,3,3], offset_b[1152],
// deform_w[64,64,3,3], deform_b[64] -> out[8,64,128,128] fp32
//
// v6 vs v5 (603us): LSU-instruction diet.
//  - weight staging via cp.async 16B (2 inst/thread/chunk, was 16 scalar)
//  - weight chunk rows padded to 72 floats (16B-aligned dst)
//  - g_sow repacked to 12-float stride -> load_w9 = 3x LDG.128 (was 5x LDG.64)

#define Bq 8
#define Cc 64
#define Hh 128
#define Ww 128
#define CO 64
#define Pp 16           // positions (w) per CTA

#define SROW 20         // samp row stride [ck][p], 16B-aligned float4 loads

// smem layout (floats)
#define SM_PATCH 0                      // [64][4][20] = 5120 (recycled in ph5)
#define SM_SAMP  5120                   // samp [576][20] = 11520
#define SM_RED   (SM_SAMP+11520)        // [8][16] = 128
#define SM_INVS  (SM_RED+128)           // [16]
#define SM_TOTAL (SM_INVS+16)           // 16784 floats
#define SMEM_BYTES (SM_TOTAL * 4)       // 67,136 B -> 3 CTAs/SM

// phase-5 recycled region overlaying patch (5120 floats available)
#define WROW 72         // padded weight row stride (16B-aligned)
#define WCH0 0          // [32 ckl][72] = 2304
#define WCH1 2304       // 2304  (total 4608 <= 5120)
// obuf (3 x 1024 = 3072) overlays WCH0+WCH1 after the post-mainloop barrier

__device__ float g_wtT[576 * 64];        // wtT[ck][o] = deform_w[o][ck]
__device__ float g_sow[64 * 18 * 12];    // per (c,j): {w[9], bias, pad, pad}

__global__ void prep_kernel(const float* __restrict__ dw,
                            const float* __restrict__ ow,
                            const float* __restrict__ obv)
{
    int i = blockIdx.x * 256 + threadIdx.x;
    if (i < 576 * 64) {
        int ck = i >> 6, o = i & 63;
        g_wtT[i] = dw[o * 576 + ck];
    }
    if (i < 64 * 18 * 12) {
        int cj = i / 12, m = i - cj * 12;
        float v = 0.0f;
        if (m < 9)       v = ow[cj * 9 + m];
        else if (m == 9) v = obv[cj];
        g_sow[i] = v;
    }
}

__device__ __forceinline__ void load_w9(const float* wc, int j,
                                        float w9[9], float& bias)
{
    float4 a = __ldg((const float4*)(wc + j * 12 + 0));
    float4 b = __ldg((const float4*)(wc + j * 12 + 4));
    float4 c = __ldg((const float4*)(wc + j * 12 + 8));
    w9[0] = a.x; w9[1] = a.y; w9[2] = a.z; w9[3] = a.w;
    w9[4] = b.x; w9[5] = b.y; w9[6] = b.z; w9[7] = b.w;
    w9[8] = c.x; bias = c.y;
}

__device__ __forceinline__ void cp16(uint32_t dst_smem, const float* src)
{
    asm volatile("cp.async.ca.shared.global [%0], [%1], 16;\n"
                 :: "r"(dst_smem), "l"(src) : "memory");
}
__device__ __forceinline__ void cp_commit()
{
    asm volatile("cp.async.commit_group;\n" ::: "memory");
}
__device__ __forceinline__ void cp_wait0()
{
    asm volatile("cp.async.wait_group 0;\n" ::: "memory");
}

__global__ __launch_bounds__(256, 3)
void deform_fused_kernel(const float* __restrict__ x,
                         const float* __restrict__ db,
                         float* __restrict__ out)
{
    extern __shared__ float sm[];
    float* patch = sm + SM_PATCH;
    float* samp  = sm + SM_SAMP;
    float* red   = sm + SM_RED;
    float* invS  = sm + SM_INVS;

    const int t  = threadIdx.x;
    const int w0 = blockIdx.x * Pp;
    const int h  = blockIdx.y;
    const int b  = blockIdx.z;

    // ---- Phase 1: load 4x20 zero-padded x patch per channel ----
    {
        const float* xb = x + (size_t)b * Cc * Hh * Ww;
        for (int i = t; i < 5120; i += 256) {
            int c   = i / 80;
            int r2  = i - c * 80;
            int r   = r2 / 20;
            int col = r2 - r * 20;
            int gy = h - 1 + r;
            int gx = w0 - 1 + col;
            float v = 0.0f;
            if (gy >= 0 && gy < Hh && gx >= 0 && gx < Ww)
                v = xb[(size_t)c * (Hh * Ww) + gy * Ww + gx];
            patch[i] = v;
        }
    }
    __syncthreads();

    // thread mapping for passes A/B: channel c, 4 positions pA..pA+3
    const int c  = t >> 2;
    const int pA = (t & 3) * 4;
    const float* wc = g_sow + c * 216;

    // ---- Pass A: conv -> exp -> per-position sums ----
    float sums[4] = {0.f, 0.f, 0.f, 0.f};
    {
        float pv3[3][6];
        #pragma unroll
        for (int r = 0; r < 3; r++)
            #pragma unroll
            for (int s = 0; s < 6; s++)
                pv3[r][s] = patch[(c * 4 + r) * 20 + pA + s];

        #pragma unroll
        for (int j = 0; j < 18; j++) {
            float w9[9], bias;
            load_w9(wc, j, w9, bias);
            float e[4] = {bias, bias, bias, bias};
            #pragma unroll
            for (int r = 0; r < 3; r++)
                #pragma unroll
                for (int s = 0; s < 3; s++) {
                    float wv = w9[r * 3 + s];
                    #pragma unroll
                    for (int q = 0; q < 4; q++)
                        e[q] += wv * pv3[r][s + q];
                }
            #pragma unroll
            for (int q = 0; q < 4; q++)
                sums[q] += __expf(e[q]);
        }
    }
    #pragma unroll
    for (int off = 4; off <= 16; off <<= 1)
        #pragma unroll
        for (int q = 0; q < 4; q++)
            sums[q] += __shfl_xor_sync(0xffffffffu, sums[q], off);
    {
        int lane = t & 31, warp = t >> 5;
        if (lane < 4) {
            #pragma unroll
            for (int q = 0; q < 4; q++)
                red[warp * 16 + lane * 4 + q] = sums[q];
        }
    }
    __syncthreads();
    if (t < 16) {
        float s = 0.f;
        #pragma unroll
        for (int w = 0; w < 8; w++) s += red[w * 16 + t];
        invS[t] = 1.0f / s;
    }
    __syncthreads();

    float4 iv4 = *(const float4*)&invS[pA];
    float iv[4] = {iv4.x, iv4.y, iv4.z, iv4.w};

    // ---- Pass B: recompute conv/exp, bilinear sample -> samp[ck][p] ----
    {
        float pv[4][7];
        #pragma unroll
        for (int r = 0; r < 4; r++)
            #pragma unroll
            for (int s = 0; s < 7; s++)
                pv[r][s] = patch[(c * 4 + r) * 20 + pA + s];

        #pragma unroll
        for (int k = 0; k < 9; k++) {
            const int ky = k / 3, kx = k % 3;
            float ey[4], ex[4];
            #pragma unroll
            for (int half = 0; half < 2; half++) {
                float w9[9], bias;
                load_w9(wc, 2 * k + half, w9, bias);
                float e[4] = {bias, bias, bias, bias};
                #pragma unroll
                for (int r = 0; r < 3; r++)
                    #pragma unroll
                    for (int s = 0; s < 3; s++) {
                        float wv = w9[r * 3 + s];
                        #pragma unroll
                        for (int q = 0; q < 4; q++)
                            e[q] += wv * pv[r][s + q];
                    }
                #pragma unroll
                for (int q = 0; q < 4; q++) {
                    if (half == 0) ey[q] = e[q]; else ex[q] = e[q];
                }
            }
            float res[4];
            #pragma unroll
            for (int q = 0; q < 4; q++) {
                float dy = __expf(ey[q]) * iv[q];
                float dx = __expf(ex[q]) * iv[q];
                float a00 = pv[ky][q + kx],     a01 = pv[ky][q + kx + 1];
                float a10 = pv[ky + 1][q + kx], a11 = pv[ky + 1][q + kx + 1];
                float top = a00 + dx * (a01 - a00);
                float bot = a10 + dx * (a11 - a10);
                res[q] = top + dy * (bot - top);
            }
            *(float4*)&samp[(c * 9 + k) * SROW + pA] =
                make_float4(res[0], res[1], res[2], res[3]);
        }
    }
    __syncthreads();   // pass B done; patch now dead -> recycle for weights

    // ---- Phase 5: out[o][p] = sum_ck wtT[ck][o] * samp[ck][p] ----
    // 4o x 4p register block, k-split 4; 32-ck chunks double-buffered via
    // cp.async (copy of chunk cc+1 overlaps compute of chunk cc).
    float acc[4][4];
    #pragma unroll
    for (int a = 0; a < 4; a++)
        #pragma unroll
        for (int p = 0; p < 4; p++) acc[a][p] = 0.f;

    const int ks = t >> 6;            // k-slice 0..3
    const int o0 = ((t >> 2) & 15) * 4;
    const int p0 = (t & 3) * 4;

    {
        const uint32_t smbase = (uint32_t)__cvta_generic_to_shared(sm);
        // per-thread staging: 2 float4 per chunk (512 float4 / 256 threads)
        const int fi0 = t, fi1 = t + 256;
        const int d0 = (fi0 >> 4) * WROW + (fi0 & 15) * 4;   // float offset
        const int d1 = (fi1 >> 4) * WROW + (fi1 & 15) * 4;

        // stage chunk 0
        cp16(smbase + (WCH0 + d0) * 4, g_wtT + fi0 * 4);
        cp16(smbase + (WCH0 + d1) * 4, g_wtT + fi1 * 4);
        cp_commit();

        for (int cc = 0; cc < 18; cc++) {
            float* wcur = sm + ((cc & 1) ? WCH1 : WCH0);
            const uint32_t wnxt = (cc & 1) ? WCH0 : WCH1;

            cp_wait0();            // my chunk-cc copies done
            __syncthreads();       // everyone's chunk-cc copies done

            if (cc < 17) {
                const float* gsrc = g_wtT + (cc + 1) * 2048;
                cp16(smbase + (wnxt + d0) * 4, gsrc + fi0 * 4);
                cp16(smbase + (wnxt + d1) * 4, gsrc + fi1 * 4);
                cp_commit();
            }

            const int ck0 = cc * 32;
            #pragma unroll
            for (int kk = 0; kk < 8; kk++) {
                int ckl = ks * 8 + kk;
                float4 wv = *(const float4*)&wcur[ckl * WROW + o0];
                float4 sv = *(const float4*)&samp[(ck0 + ckl) * SROW + p0];
                acc[0][0] += wv.x * sv.x; acc[0][1] += wv.x * sv.y;
                acc[0][2] += wv.x * sv.z; acc[0][3] += wv.x * sv.w;
                acc[1][0] += wv.y * sv.x; acc[1][1] += wv.y * sv.y;
                acc[1][2] += wv.y * sv.z; acc[1][3] += wv.y * sv.w;
                acc[2][0] += wv.z * sv.x; acc[2][1] += wv.z * sv.y;
                acc[2][2] += wv.z * sv.z; acc[2][3] += wv.z * sv.w;
                acc[3][0] += wv.w * sv.x; acc[3][1] += wv.w * sv.y;
                acc[3][2] += wv.w * sv.z; acc[3][3] += wv.w * sv.w;
            }
        }
    }
    __syncthreads();   // all compute done before obuf overlays weight bufs

    // ---- combine k-split quarters, add bias, store (STG.128) ----
    {
        float* obuf = sm;              // 3 slices x [64][16] over WCH region
        if (ks > 0) {
            float* os = obuf + (ks - 1) * 1024;
            #pragma unroll
            for (int oo = 0; oo < 4; oo++)
                *(float4*)&os[(o0 + oo) * 16 + p0] =
                    make_float4(acc[oo][0], acc[oo][1], acc[oo][2], acc[oo][3]);
        }
        __syncthreads();
        if (ks == 0) {
            float4 bv = __ldg((const float4*)&db[o0]);
            float bvs[4] = {bv.x, bv.y, bv.z, bv.w};
            #pragma unroll
            for (int oo = 0; oo < 4; oo++) {
                int o = o0 + oo;
                float4 r0 = *(const float4*)&obuf[0 * 1024 + o * 16 + p0];
                float4 r1 = *(const float4*)&obuf[1 * 1024 + o * 16 + p0];
                float4 r2 = *(const float4*)&obuf[2 * 1024 + o * 16 + p0];
                float4 v;
                v.x = acc[oo][0] + r0.x + r1.x + r2.x + bvs[oo];
                v.y = acc[oo][1] + r0.y + r1.y + r2.y + bvs[oo];
                v.z = acc[oo][2] + r0.z + r1.z + r2.z + bvs[oo];
                v.w = acc[oo][3] + r0.w + r1.w + r2.w + bvs[oo];
                *(float4*)&out[(((size_t)b * CO + o) * Hh + h) * Ww + w0 + p0] = v;
            }
        }
    }
}

extern "C" void kernel_launch(void* const* d_in, const int* in_sizes, int n_in,
                              void* d_out, int out_size)
{
    const float* x   = (const float*)d_in[0];   // [8,64,128,128]
    const float* ow  = (const float*)d_in[1];   // [1152,1,3,3]
    const float* obv = (const float*)d_in[2];   // [1152]
    const float* dw  = (const float*)d_in[3];   // [64,64,3,3]
    const float* db  = (const float*)d_in[4];   // [64]
    float* out = (float*)d_out;                 // [8,64,128,128]

    cudaFuncSetAttribute(deform_fused_kernel,
                         cudaFuncAttributeMaxDynamicSharedMemorySize, SMEM_BYTES);

    prep_kernel<<<(576 * 64 + 255) / 256, 256>>>(dw, ow, obv);

    dim3 grid(Ww / Pp, Hh, Bq);   // (8, 128, 8) = 8192 CTAs
    deform_fused_kernel<<<grid, 256, SMEM_BYTES>>>(x, db, out);
}

// round 9
// speedup vs baseline: 2.7788x; 1.0004x over previous
#include <cuda_runtime.h>
#include <cuda_bf16.h>
#include <cstdint>

// DeformableConv2d fused kernel v6b, sm_103a.  (v6 + missing <cstdint>)
//
// x[8,64,128,128], offset_w[1152,1,3,3], offset_b[1152],
// deform_w[64,64,3,3], deform_b[64] -> out[8,64,128,128] fp32
//
// v6 vs v5 (603us): LSU-instruction diet.
//  - weight staging via cp.async 16B (2 inst/thread/chunk, was 16 scalar)
//  - weight chunk rows padded to 72 floats (16B-aligned dst)
//  - g_sow repacked to 12-float stride -> load_w9 = 3x LDG.128 (was 5x LDG.64)

#define Bq 8
#define Cc 64
#define Hh 128
#define Ww 128
#define CO 64
#define Pp 16           // positions (w) per CTA

#define SROW 20         // samp row stride [ck][p], 16B-aligned float4 loads

// smem layout (floats)
#define SM_PATCH 0                      // [64][4][20] = 5120 (recycled in ph5)
#define SM_SAMP  5120                   // samp [576][20] = 11520
#define SM_RED   (SM_SAMP+11520)        // [8][16] = 128
#define SM_INVS  (SM_RED+128)           // [16]
#define SM_TOTAL (SM_INVS+16)           // 16784 floats
#define SMEM_BYTES (SM_TOTAL * 4)       // 67,136 B -> 3 CTAs/SM

// phase-5 recycled region overlaying patch (5120 floats available)
#define WROW 72         // padded weight row stride (16B-aligned)
#define WCH0 0          // [32 ckl][72] = 2304
#define WCH1 2304       // 2304  (total 4608 <= 5120)
// obuf (3 x 1024 = 3072) overlays WCH0+WCH1 after the post-mainloop barrier

__device__ float g_wtT[576 * 64];        // wtT[ck][o] = deform_w[o][ck]
__device__ float g_sow[64 * 18 * 12];    // per (c,j): {w[9], bias, pad, pad}

__global__ void prep_kernel(const float* __restrict__ dw,
                            const float* __restrict__ ow,
                            const float* __restrict__ obv)
{
    int i = blockIdx.x * 256 + threadIdx.x;
    if (i < 576 * 64) {
        int ck = i >> 6, o = i & 63;
        g_wtT[i] = dw[o * 576 + ck];
    }
    if (i < 64 * 18 * 12) {
        int cj = i / 12, m = i - cj * 12;
        float v = 0.0f;
        if (m < 9)       v = ow[cj * 9 + m];
        else if (m == 9) v = obv[cj];
        g_sow[i] = v;
    }
}

__device__ __forceinline__ void load_w9(const float* wc, int j,
                                        float w9[9], float& bias)
{
    float4 a = __ldg((const float4*)(wc + j * 12 + 0));
    float4 b = __ldg((const float4*)(wc + j * 12 + 4));
    float4 c = __ldg((const float4*)(wc + j * 12 + 8));
    w9[0] = a.x; w9[1] = a.y; w9[2] = a.z; w9[3] = a.w;
    w9[4] = b.x; w9[5] = b.y; w9[6] = b.z; w9[7] = b.w;
    w9[8] = c.x; bias = c.y;
}

__device__ __forceinline__ void cp16(uint32_t dst_smem, const float* src)
{
    asm volatile("cp.async.ca.shared.global [%0], [%1], 16;\n"
                 :: "r"(dst_smem), "l"(src) : "memory");
}
__device__ __forceinline__ void cp_commit()
{
    asm volatile("cp.async.commit_group;\n" ::: "memory");
}
__device__ __forceinline__ void cp_wait0()
{
    asm volatile("cp.async.wait_group 0;\n" ::: "memory");
}

__global__ __launch_bounds__(256, 3)
void deform_fused_kernel(const float* __restrict__ x,
                         const float* __restrict__ db,
                         float* __restrict__ out)
{
    extern __shared__ float sm[];
    float* patch = sm + SM_PATCH;
    float* samp  = sm + SM_SAMP;
    float* red   = sm + SM_RED;
    float* invS  = sm + SM_INVS;

    const int t  = threadIdx.x;
    const int w0 = blockIdx.x * Pp;
    const int h  = blockIdx.y;
    const int b  = blockIdx.z;

    // ---- Phase 1: load 4x20 zero-padded x patch per channel ----
    {
        const float* xb = x + (size_t)b * Cc * Hh * Ww;
        for (int i = t; i < 5120; i += 256) {
            int c   = i / 80;
            int r2  = i - c * 80;
            int r   = r2 / 20;
            int col = r2 - r * 20;
            int gy = h - 1 + r;
            int gx = w0 - 1 + col;
            float v = 0.0f;
            if (gy >= 0 && gy < Hh && gx >= 0 && gx < Ww)
                v = xb[(size_t)c * (Hh * Ww) + gy * Ww + gx];
            patch[i] = v;
        }
    }
    __syncthreads();

    // thread mapping for passes A/B: channel c, 4 positions pA..pA+3
    const int c  = t >> 2;
    const int pA = (t & 3) * 4;
    const float* wc = g_sow + c * 216;

    // ---- Pass A: conv -> exp -> per-position sums ----
    float sums[4] = {0.f, 0.f, 0.f, 0.f};
    {
        float pv3[3][6];
        #pragma unroll
        for (int r = 0; r < 3; r++)
            #pragma unroll
            for (int s = 0; s < 6; s++)
                pv3[r][s] = patch[(c * 4 + r) * 20 + pA + s];

        #pragma unroll
        for (int j = 0; j < 18; j++) {
            float w9[9], bias;
            load_w9(wc, j, w9, bias);
            float e[4] = {bias, bias, bias, bias};
            #pragma unroll
            for (int r = 0; r < 3; r++)
                #pragma unroll
                for (int s = 0; s < 3; s++) {
                    float wv = w9[r * 3 + s];
                    #pragma unroll
                    for (int q = 0; q < 4; q++)
                        e[q] += wv * pv3[r][s + q];
                }
            #pragma unroll
            for (int q = 0; q < 4; q++)
                sums[q] += __expf(e[q]);
        }
    }
    #pragma unroll
    for (int off = 4; off <= 16; off <<= 1)
        #pragma unroll
        for (int q = 0; q < 4; q++)
            sums[q] += __shfl_xor_sync(0xffffffffu, sums[q], off);
    {
        int lane = t & 31, warp = t >> 5;
        if (lane < 4) {
            #pragma unroll
            for (int q = 0; q < 4; q++)
                red[warp * 16 + lane * 4 + q] = sums[q];
        }
    }
    __syncthreads();
    if (t < 16) {
        float s = 0.f;
        #pragma unroll
        for (int w = 0; w < 8; w++) s += red[w * 16 + t];
        invS[t] = 1.0f / s;
    }
    __syncthreads();

    float4 iv4 = *(const float4*)&invS[pA];
    float iv[4] = {iv4.x, iv4.y, iv4.z, iv4.w};

    // ---- Pass B: recompute conv/exp, bilinear sample -> samp[ck][p] ----
    {
        float pv[4][7];
        #pragma unroll
        for (int r = 0; r < 4; r++)
            #pragma unroll
            for (int s = 0; s < 7; s++)
                pv[r][s] = patch[(c * 4 + r) * 20 + pA + s];

        #pragma unroll
        for (int k = 0; k < 9; k++) {
            const int ky = k / 3, kx = k % 3;
            float ey[4], ex[4];
            #pragma unroll
            for (int half = 0; half < 2; half++) {
                float w9[9], bias;
                load_w9(wc, 2 * k + half, w9, bias);
                float e[4] = {bias, bias, bias, bias};
                #pragma unroll
                for (int r = 0; r < 3; r++)
                    #pragma unroll
                    for (int s = 0; s < 3; s++) {
                        float wv = w9[r * 3 + s];
                        #pragma unroll
                        for (int q = 0; q < 4; q++)
                            e[q] += wv * pv[r][s + q];
                    }
                #pragma unroll
                for (int q = 0; q < 4; q++) {
                    if (half == 0) ey[q] = e[q]; else ex[q] = e[q];
                }
            }
            float res[4];
            #pragma unroll
            for (int q = 0; q < 4; q++) {
                float dy = __expf(ey[q]) * iv[q];
                float dx = __expf(ex[q]) * iv[q];
                float a00 = pv[ky][q + kx],     a01 = pv[ky][q + kx + 1];
                float a10 = pv[ky + 1][q + kx], a11 = pv[ky + 1][q + kx + 1];
                float top = a00 + dx * (a01 - a00);
                float bot = a10 + dx * (a11 - a10);
                res[q] = top + dy * (bot - top);
            }
            *(float4*)&samp[(c * 9 + k) * SROW + pA] =
                make_float4(res[0], res[1], res[2], res[3]);
        }
    }
    __syncthreads();   // pass B done; patch now dead -> recycle for weights

    // ---- Phase 5: out[o][p] = sum_ck wtT[ck][o] * samp[ck][p] ----
    // 4o x 4p register block, k-split 4; 32-ck chunks double-buffered via
    // cp.async (copy of chunk cc+1 overlaps compute of chunk cc).
    float acc[4][4];
    #pragma unroll
    for (int a = 0; a < 4; a++)
        #pragma unroll
        for (int p = 0; p < 4; p++) acc[a][p] = 0.f;

    const int ks = t >> 6;            // k-slice 0..3
    const int o0 = ((t >> 2) & 15) * 4;
    const int p0 = (t & 3) * 4;

    {
        const uint32_t smbase = (uint32_t)__cvta_generic_to_shared(sm);
        // per-thread staging: 2 float4 per chunk (512 float4 / 256 threads)
        const int fi0 = t, fi1 = t + 256;
        const int d0 = (fi0 >> 4) * WROW + (fi0 & 15) * 4;   // float offset
        const int d1 = (fi1 >> 4) * WROW + (fi1 & 15) * 4;

        // stage chunk 0
        cp16(smbase + (WCH0 + d0) * 4, g_wtT + fi0 * 4);
        cp16(smbase + (WCH0 + d1) * 4, g_wtT + fi1 * 4);
        cp_commit();

        for (int cc = 0; cc < 18; cc++) {
            float* wcur = sm + ((cc & 1) ? WCH1 : WCH0);
            const uint32_t wnxt = (cc & 1) ? WCH0 : WCH1;

            cp_wait0();            // my chunk-cc copies done
            __syncthreads();       // everyone's chunk-cc copies done

            if (cc < 17) {
                const float* gsrc = g_wtT + (cc + 1) * 2048;
                cp16(smbase + (wnxt + d0) * 4, gsrc + fi0 * 4);
                cp16(smbase + (wnxt + d1) * 4, gsrc + fi1 * 4);
                cp_commit();
            }

            const int ck0 = cc * 32;
            #pragma unroll
            for (int kk = 0; kk < 8; kk++) {
                int ckl = ks * 8 + kk;
                float4 wv = *(const float4*)&wcur[ckl * WROW + o0];
                float4 sv = *(const float4*)&samp[(ck0 + ckl) * SROW + p0];
                acc[0][0] += wv.x * sv.x; acc[0][1] += wv.x * sv.y;
                acc[0][2] += wv.x * sv.z; acc[0][3] += wv.x * sv.w;
                acc[1][0] += wv.y * sv.x; acc[1][1] += wv.y * sv.y;
                acc[1][2] += wv.y * sv.z; acc[1][3] += wv.y * sv.w;
                acc[2][0] += wv.z * sv.x; acc[2][1] += wv.z * sv.y;
                acc[2][2] += wv.z * sv.z; acc[2][3] += wv.z * sv.w;
                acc[3][0] += wv.w * sv.x; acc[3][1] += wv.w * sv.y;
                acc[3][2] += wv.w * sv.z; acc[3][3] += wv.w * sv.w;
            }
        }
    }
    __syncthreads();   // all compute done before obuf overlays weight bufs

    // ---- combine k-split quarters, add bias, store (STG.128) ----
    {
        float* obuf = sm;              // 3 slices x [64][16] over WCH region
        if (ks > 0) {
            float* os = obuf + (ks - 1) * 1024;
            #pragma unroll
            for (int oo = 0; oo < 4; oo++)
                *(float4*)&os[(o0 + oo) * 16 + p0] =
                    make_float4(acc[oo][0], acc[oo][1], acc[oo][2], acc[oo][3]);
        }
        __syncthreads();
        if (ks == 0) {
            float4 bv = __ldg((const float4*)&db[o0]);
            float bvs[4] = {bv.x, bv.y, bv.z, bv.w};
            #pragma unroll
            for (int oo = 0; oo < 4; oo++) {
                int o = o0 + oo;
                float4 r0 = *(const float4*)&obuf[0 * 1024 + o * 16 + p0];
                float4 r1 = *(const float4*)&obuf[1 * 1024 + o * 16 + p0];
                float4 r2 = *(const float4*)&obuf[2 * 1024 + o * 16 + p0];
                float4 v;
                v.x = acc[oo][0] + r0.x + r1.x + r2.x + bvs[oo];
                v.y = acc[oo][1] + r0.y + r1.y + r2.y + bvs[oo];
                v.z = acc[oo][2] + r0.z + r1.z + r2.z + bvs[oo];
                v.w = acc[oo][3] + r0.w + r1.w + r2.w + bvs[oo];
                *(float4*)&out[(((size_t)b * CO + o) * Hh + h) * Ww + w0 + p0] = v;
            }
        }
    }
}

extern "C" void kernel_launch(void* const* d_in, const int* in_sizes, int n_in,
                              void* d_out, int out_size)
{
    const float* x   = (const float*)d_in[0];   // [8,64,128,128]
    const float* ow  = (const float*)d_in[1];   // [1152,1,3,3]
    const float* obv = (const float*)d_in[2];   // [1152]
    const float* dw  = (const float*)d_in[3];   // [64,64,3,3]
    const float* db  = (const float*)d_in[4];   // [64]
    float* out = (float*)d_out;                 // [8,64,128,128]

    cudaFuncSetAttribute(deform_fused_kernel,
                         cudaFuncAttributeMaxDynamicSharedMemorySize, SMEM_BYTES);

    prep_kernel<<<(576 * 64 + 255) / 256, 256>>>(dw, ow, obv);

    dim3 grid(Ww / Pp, Hh, Bq);   // (8, 128, 8) = 8192 CTAs
    deform_fused_kernel<<<grid, 256, SMEM_BYTES>>>(x, db, out);
}

// round 11
// speedup vs baseline: 3.7019x; 1.3322x over previous
#include <cuda_runtime.h>
#include <cstdint>

// DeformableConv2d v8, sm_103a. v6b pre-phase (518us kernel) + phase-5 GEMM
// replaced by warp-level mma.sync tf32 (tcgen05 unavailable: harness PTX
// target is compute_103, which rejects tcgen05.*).
//
// D[16 p][64 o] = A[16 p][576 ck] x B[576][64], K = 72 steps of 8.
// Warp w -> n-tile w (outputs 8w..8w+7), 72 mma, 4 fp32 accumulators.
// A stored by pass B directly in m16n8k8 fragment order (tf32 bits);
// B pre-packed in fragment order in gmem by prep kernel.

#define Bq 8
#define Cc 64
#define Hh 128
#define Ww 128
#define CO 64
#define Pp 16

// smem layout (floats)
#define SM_PATCH 0                       // [64][4][20] = 5120
#define SM_SAF   5120                    // A frags [72 kb][32 lane][4 reg] = 9216
#define SM_RED   (SM_SAF+9216)           // [8][16] = 128
#define SM_INVS  (SM_RED+128)            // [16]
#define SM_TOTAL (SM_INVS+16)            // 14480 floats
#define SMEM_BYTES (SM_TOTAL*4)          // 57,920 B

__device__ uint32_t g_bfrag[8 * 72 * 32 * 2];  // [ntile][kb][lane][2] tf32 bits
__device__ float    g_sow[64 * 18 * 12];       // per (c,j): {w[9], bias, pad, pad}

__device__ __forceinline__ uint32_t f2tf32(float v)
{
    uint32_t u;
    asm("cvt.rna.tf32.f32 %0, %1;" : "=r"(u) : "f"(v));
    return u;
}

__global__ void prep_kernel(const float* __restrict__ dw,
                            const float* __restrict__ ow,
                            const float* __restrict__ obv)
{
    int i = blockIdx.x * 256 + threadIdx.x;
    if (i < 8 * 72 * 64) {
        int nt  = i / (72 * 64);
        int rem = i - nt * 72 * 64;
        int kb  = rem >> 6;
        int le  = rem & 63;
        int lane = le >> 1, ii = le & 1;
        int g = lane >> 2, tig = lane & 3;
        int o  = nt * 8 + g;
        int ck = kb * 8 + tig + ii * 4;        // < 576 always
        g_bfrag[i] = f2tf32(dw[o * 576 + ck]);
    }
    if (i < 64 * 18 * 12) {
        int cj = i / 12, m = i - cj * 12;
        float v = 0.0f;
        if (m < 9) v = ow[cj * 9 + m]; else if (m == 9) v = obv[cj];
        g_sow[i] = v;
    }
}

__device__ __forceinline__ void load_w9(const float* wc, int j,
                                        float w9[9], float& bias)
{
    float4 a = __ldg((const float4*)(wc + j * 12 + 0));
    float4 b = __ldg((const float4*)(wc + j * 12 + 4));
    float4 c = __ldg((const float4*)(wc + j * 12 + 8));
    w9[0]=a.x; w9[1]=a.y; w9[2]=a.z; w9[3]=a.w;
    w9[4]=b.x; w9[5]=b.y; w9[6]=b.z; w9[7]=b.w; w9[8]=c.x; bias=c.y;
}

__global__ __launch_bounds__(256, 3)
void deform_fused_kernel(const float* __restrict__ x,
                         const float* __restrict__ db,
                         float* __restrict__ out)
{
    extern __shared__ float sm[];
    float* patch = sm + SM_PATCH;
    float* red   = sm + SM_RED;
    float* invS  = sm + SM_INVS;
    uint32_t* saf = (uint32_t*)sm + SM_SAF;

    const int t  = threadIdx.x;
    const int w0 = blockIdx.x * Pp;
    const int h  = blockIdx.y;
    const int b  = blockIdx.z;

    // ---- Phase 1: load 4x20 zero-padded x patch per channel ----
    {
        const float* xb = x + (size_t)b * Cc * Hh * Ww;
        for (int i = t; i < 5120; i += 256) {
            int c   = i / 80;
            int r2  = i - c * 80;
            int r   = r2 / 20;
            int col = r2 - r * 20;
            int gy = h - 1 + r;
            int gx = w0 - 1 + col;
            float v = 0.0f;
            if (gy >= 0 && gy < Hh && gx >= 0 && gx < Ww)
                v = xb[(size_t)c * (Hh * Ww) + gy * Ww + gx];
            patch[i] = v;
        }
    }
    __syncthreads();

    const int c  = t >> 2;
    const int pA = (t & 3) * 4;
    const float* wc = g_sow + c * 216;

    // ---- Pass A: conv -> exp -> per-position sums ----
    float sums[4] = {0.f, 0.f, 0.f, 0.f};
    {
        float pv3[3][6];
        #pragma unroll
        for (int r = 0; r < 3; r++)
            #pragma unroll
            for (int s = 0; s < 6; s++)
                pv3[r][s] = patch[(c * 4 + r) * 20 + pA + s];

        #pragma unroll
        for (int j = 0; j < 18; j++) {
            float w9[9], bias;
            load_w9(wc, j, w9, bias);
            float e[4] = {bias, bias, bias, bias};
            #pragma unroll
            for (int r = 0; r < 3; r++)
                #pragma unroll
                for (int s = 0; s < 3; s++) {
                    float wv = w9[r * 3 + s];
                    #pragma unroll
                    for (int q = 0; q < 4; q++)
                        e[q] += wv * pv3[r][s + q];
                }
            #pragma unroll
            for (int q = 0; q < 4; q++)
                sums[q] += __expf(e[q]);
        }
    }
    #pragma unroll
    for (int off = 4; off <= 16; off <<= 1)
        #pragma unroll
        for (int q = 0; q < 4; q++)
            sums[q] += __shfl_xor_sync(0xffffffffu, sums[q], off);
    {
        int lane = t & 31, warp = t >> 5;
        if (lane < 4) {
            #pragma unroll
            for (int q = 0; q < 4; q++)
                red[warp * 16 + lane * 4 + q] = sums[q];
        }
    }
    __syncthreads();
    if (t < 16) {
        float s = 0.f;
        #pragma unroll
        for (int w = 0; w < 8; w++) s += red[w * 16 + t];
        invS[t] = 1.0f / s;
    }
    __syncthreads();

    float4 iv4 = *(const float4*)&invS[pA];
    float iv[4] = {iv4.x, iv4.y, iv4.z, iv4.w};

    // ---- Pass B: recompute conv/exp, bilinear -> A fragments (tf32) ----
    {
        float pv[4][7];
        #pragma unroll
        for (int r = 0; r < 4; r++)
            #pragma unroll
            for (int s = 0; s < 7; s++)
                pv[r][s] = patch[(c * 4 + r) * 20 + pA + s];

        #pragma unroll
        for (int k = 0; k < 9; k++) {
            const int ky = k / 3, kx = k % 3;
            const int ck = c * 9 + k;
            const int kb = ck >> 3;
            const int cc8 = ck & 7;
            const int tig = cc8 & 3, halfk = cc8 >> 2;
            float ey[4], ex[4];
            #pragma unroll
            for (int half = 0; half < 2; half++) {
                float w9[9], bias;
                load_w9(wc, 2 * k + half, w9, bias);
                float e[4] = {bias, bias, bias, bias};
                #pragma unroll
                for (int r = 0; r < 3; r++)
                    #pragma unroll
                    for (int s = 0; s < 3; s++) {
                        float wv = w9[r * 3 + s];
                        #pragma unroll
                        for (int q = 0; q < 4; q++)
                            e[q] += wv * pv[r][s + q];
                    }
                #pragma unroll
                for (int q = 0; q < 4; q++) {
                    if (half == 0) ey[q] = e[q]; else ex[q] = e[q];
                }
            }
            #pragma unroll
            for (int q = 0; q < 4; q++) {
                float dy = __expf(ey[q]) * iv[q];
                float dx = __expf(ex[q]) * iv[q];
                float a00 = pv[ky][q + kx],     a01 = pv[ky][q + kx + 1];
                float a10 = pv[ky + 1][q + kx], a11 = pv[ky + 1][q + kx + 1];
                float top = a00 + dx * (a01 - a00);
                float bot = a10 + dx * (a11 - a10);
                float res = top + dy * (bot - top);
                int p = pA + q;
                int lane = (p & 7) * 4 + tig;
                int reg  = halfk * 2 + (p >> 3);
                saf[kb * 128 + lane * 4 + reg] = f2tf32(res);
            }
        }
    }
    __syncthreads();

    // ---- Phase 5: mma.sync tf32. Warp w = n-tile w; 72 k-steps ----
    {
        const int nt = t >> 5;
        const int l  = t & 31;
        float a0 = 0.f, a1 = 0.f, a2 = 0.f, a3 = 0.f;
        const uint32_t bbase = nt * 4608 + l * 2;

        #pragma unroll 4
        for (int kb = 0; kb < 72; kb++) {
            uint4 av = *(const uint4*)&saf[kb * 128 + l * 4];
            uint2 bv = __ldg((const uint2*)&g_bfrag[bbase + kb * 64]);
            asm("mma.sync.aligned.m16n8k8.row.col.f32.tf32.tf32.f32 "
                "{%0,%1,%2,%3}, {%4,%5,%6,%7}, {%8,%9}, {%0,%1,%2,%3};"
                : "+f"(a0), "+f"(a1), "+f"(a2), "+f"(a3)
                : "r"(av.x), "r"(av.y), "r"(av.z), "r"(av.w),
                  "r"(bv.x), "r"(bv.y));
        }

        // c0:(row g, col 2tig) c1:(g, 2tig+1) c2:(g+8, 2tig) c3:(g+8, 2tig+1)
        const int g = l >> 2, tig = l & 3;
        const int o = nt * 8 + tig * 2;
        float b0 = __ldg(&db[o]), b1 = __ldg(&db[o + 1]);
        size_t base = ((size_t)(b * CO + o) * Hh + h) * Ww + w0;
        out[base + g]               = a0 + b0;
        out[base + Hh * Ww + g]     = a1 + b1;
        out[base + g + 8]           = a2 + b0;
        out[base + Hh * Ww + g + 8] = a3 + b1;
    }
}

extern "C" void kernel_launch(void* const* d_in, const int* in_sizes, int n_in,
                              void* d_out, int out_size)
{
    const float* x   = (const float*)d_in[0];   // [8,64,128,128]
    const float* ow  = (const float*)d_in[1];   // [1152,1,3,3]
    const float* obv = (const float*)d_in[2];   // [1152]
    const float* dw  = (const float*)d_in[3];   // [64,64,3,3]
    const float* db  = (const float*)d_in[4];   // [64]
    float* out = (float*)d_out;                 // [8,64,128,128]

    cudaFuncSetAttribute(deform_fused_kernel,
                         cudaFuncAttributeMaxDynamicSharedMemorySize, SMEM_BYTES);

    prep_kernel<<<144, 256>>>(dw, ow, obv);

    dim3 grid(Ww / Pp, Hh, Bq);   // (8, 128, 8) = 8192 CTAs
    deform_fused_kernel<<<grid, 256, SMEM_BYTES>>>(x, db, out);
}

// round 13
// speedup vs baseline: 3.8319x; 1.0351x over previous
#include <cuda_runtime.h>
#include <cuda_fp16.h>
#include <cstdint>

// DeformableConv2d v9b, sm_103a.  (v9 with valid fp16 casts)
// v8 (389us) minus the pass-B conv recompute: pass A caches exp(e) in smem
// as __half2; pass B reads them back. A-fragments (saf) overlay the dead
// patch region after a barrier -> smem 74.3KB, still 3 CTAs/SM.
// GEMM: warp-level mma.sync m16n8k8 tf32 (tcgen05 rejected by the harness's
// compute_103 PTX target).

#define Bq 8
#define Cc 64
#define Hh 128
#define Ww 128
#define CO 64
#define Pp 16

// smem layout (float slots)
#define U_F     0        // union: patch [64][4][20]=5120  /  saf 9216
#define EA_F    9216     // exp(e) __half2: [64 c][18 j][8 h2] = 9216 slots
#define RED_F   18432    // [8][16] = 128
#define INVS_F  18560    // [16]
#define SM_TOTAL 18576
#define SMEM_BYTES (SM_TOTAL*4)      // 74,304 B -> 3 CTAs/SM

__device__ uint32_t g_bfrag[8 * 72 * 32 * 2];  // [ntile][kb][lane][2] tf32 bits
__device__ float    g_sow[64 * 18 * 12];       // per (c,j): {w[9], bias, pad, pad}

__device__ __forceinline__ uint32_t f2tf32(float v)
{
    uint32_t u;
    asm("cvt.rna.tf32.f32 %0, %1;" : "=r"(u) : "f"(v));
    return u;
}

__global__ void prep_kernel(const float* __restrict__ dw,
                            const float* __restrict__ ow,
                            const float* __restrict__ obv)
{
    int i = blockIdx.x * 256 + threadIdx.x;
    if (i < 8 * 72 * 64) {
        int nt  = i / (72 * 64);
        int rem = i - nt * 72 * 64;
        int kb  = rem >> 6;
        int le  = rem & 63;
        int lane = le >> 1, ii = le & 1;
        int g = lane >> 2, tig = lane & 3;
        int o  = nt * 8 + g;
        int ck = kb * 8 + tig + ii * 4;
        g_bfrag[i] = f2tf32(dw[o * 576 + ck]);
    }
    if (i < 64 * 18 * 12) {
        int cj = i / 12, m = i - cj * 12;
        float v = 0.0f;
        if (m < 9) v = ow[cj * 9 + m]; else if (m == 9) v = obv[cj];
        g_sow[i] = v;
    }
}

__device__ __forceinline__ void load_w9(const float* wc, int j,
                                        float w9[9], float& bias)
{
    float4 a = __ldg((const float4*)(wc + j * 12 + 0));
    float4 b = __ldg((const float4*)(wc + j * 12 + 4));
    float4 c = __ldg((const float4*)(wc + j * 12 + 8));
    w9[0]=a.x; w9[1]=a.y; w9[2]=a.z; w9[3]=a.w;
    w9[4]=b.x; w9[5]=b.y; w9[6]=b.z; w9[7]=b.w; w9[8]=c.x; bias=c.y;
}

__global__ __launch_bounds__(256, 3)
void deform_fused_kernel(const float* __restrict__ x,
                         const float* __restrict__ db,
                         float* __restrict__ out)
{
    extern __shared__ float sm[];
    float*    patch = sm + U_F;                  // phase 1 .. pass B pv load
    uint32_t* saf   = (uint32_t*)sm + U_F;       // pass B .. GEMM (overlay)
    __half2*  eah   = (__half2*)(sm + EA_F);     // exp cache [c][j][8 h2]
    float*    red   = sm + RED_F;
    float*    invS  = sm + INVS_F;

    const int t  = threadIdx.x;
    const int w0 = blockIdx.x * Pp;
    const int h  = blockIdx.y;
    const int b  = blockIdx.z;

    // ---- Phase 1: load 4x20 zero-padded x patch per channel ----
    {
        const float* xb = x + (size_t)b * Cc * Hh * Ww;
        for (int i = t; i < 5120; i += 256) {
            int c   = i / 80;
            int r2  = i - c * 80;
            int r   = r2 / 20;
            int col = r2 - r * 20;
            int gy = h - 1 + r;
            int gx = w0 - 1 + col;
            float v = 0.0f;
            if (gy >= 0 && gy < Hh && gx >= 0 && gx < Ww)
                v = xb[(size_t)c * (Hh * Ww) + gy * Ww + gx];
            patch[i] = v;
        }
    }
    __syncthreads();

    const int c  = t >> 2;
    const int pA = (t & 3) * 4;
    const float* wc = g_sow + c * 216;

    // ---- Pass A: conv -> exp -> cache exp (__half2) + per-position sums ----
    float sums[4] = {0.f, 0.f, 0.f, 0.f};
    {
        float pv3[3][6];
        #pragma unroll
        for (int r = 0; r < 3; r++)
            #pragma unroll
            for (int s = 0; s < 6; s++)
                pv3[r][s] = patch[(c * 4 + r) * 20 + pA + s];

        #pragma unroll
        for (int j = 0; j < 18; j++) {
            float w9[9], bias;
            load_w9(wc, j, w9, bias);
            float e[4] = {bias, bias, bias, bias};
            #pragma unroll
            for (int r = 0; r < 3; r++)
                #pragma unroll
                for (int s = 0; s < 3; s++) {
                    float wv = w9[r * 3 + s];
                    #pragma unroll
                    for (int q = 0; q < 4; q++)
                        e[q] += wv * pv3[r][s + q];
                }
            float x0 = __expf(e[0]), x1 = __expf(e[1]);
            float x2 = __expf(e[2]), x3 = __expf(e[3]);
            sums[0] += x0; sums[1] += x1; sums[2] += x2; sums[3] += x3;
            __half2 h01 = __floats2half2_rn(x0, x1);
            __half2 h23 = __floats2half2_rn(x2, x3);
            __half2* dst = &eah[(c * 18 + j) * 8 + (pA >> 1)];
            dst[0] = h01;
            dst[1] = h23;
        }
    }
    #pragma unroll
    for (int off = 4; off <= 16; off <<= 1)
        #pragma unroll
        for (int q = 0; q < 4; q++)
            sums[q] += __shfl_xor_sync(0xffffffffu, sums[q], off);
    {
        int lane = t & 31, warp = t >> 5;
        if (lane < 4) {
            #pragma unroll
            for (int q = 0; q < 4; q++)
                red[warp * 16 + lane * 4 + q] = sums[q];
        }
    }
    __syncthreads();
    if (t < 16) {
        float s = 0.f;
        #pragma unroll
        for (int w = 0; w < 8; w++) s += red[w * 16 + t];
        invS[t] = 1.0f / s;
    }
    __syncthreads();

    float4 iv4 = *(const float4*)&invS[pA];
    float iv[4] = {iv4.x, iv4.y, iv4.z, iv4.w};

    // ---- Pass B: read cached exp, bilinear -> A fragments (tf32) ----
    {
        float pv[4][7];
        #pragma unroll
        for (int r = 0; r < 4; r++)
            #pragma unroll
            for (int s = 0; s < 7; s++)
                pv[r][s] = patch[(c * 4 + r) * 20 + pA + s];
        __syncthreads();     // all pv loaded before saf overlays patch

        #pragma unroll
        for (int k = 0; k < 9; k++) {
            const int ky = k / 3, kx = k % 3;
            const int ck = c * 9 + k;
            const int kb = ck >> 3;
            const int cc8 = ck & 7;
            const int tig = cc8 & 3, halfk = cc8 >> 2;

            const __half2* py = &eah[(c * 18 + 2 * k)     * 8 + (pA >> 1)];
            const __half2* px = &eah[(c * 18 + 2 * k + 1) * 8 + (pA >> 1)];
            float2 y01 = __half22float2(py[0]);
            float2 y23 = __half22float2(py[1]);
            float2 x01 = __half22float2(px[0]);
            float2 x23 = __half22float2(px[1]);
            float eyv[4] = {y01.x, y01.y, y23.x, y23.y};
            float exv[4] = {x01.x, x01.y, x23.x, x23.y};

            #pragma unroll
            for (int q = 0; q < 4; q++) {
                float dy = eyv[q] * iv[q];
                float dx = exv[q] * iv[q];
                float a00 = pv[ky][q + kx],     a01 = pv[ky][q + kx + 1];
                float a10 = pv[ky + 1][q + kx], a11 = pv[ky + 1][q + kx + 1];
                float top = a00 + dx * (a01 - a00);
                float bot = a10 + dx * (a11 - a10);
                float res = top + dy * (bot - top);
                int p = pA + q;
                int lane = (p & 7) * 4 + tig;
                int reg  = halfk * 2 + (p >> 3);
                saf[kb * 128 + lane * 4 + reg] = f2tf32(res);
            }
        }
    }
    __syncthreads();

    // ---- Phase 5: mma.sync tf32. Warp w = n-tile w; 72 k-steps ----
    {
        const int nt = t >> 5;
        const int l  = t & 31;
        float a0 = 0.f, a1 = 0.f, a2 = 0.f, a3 = 0.f;
        const uint32_t bbase = nt * 4608 + l * 2;

        #pragma unroll 4
        for (int kb = 0; kb < 72; kb++) {
            uint4 av = *(const uint4*)&saf[kb * 128 + l * 4];
            uint2 bv = __ldg((const uint2*)&g_bfrag[bbase + kb * 64]);
            asm("mma.sync.aligned.m16n8k8.row.col.f32.tf32.tf32.f32 "
                "{%0,%1,%2,%3}, {%4,%5,%6,%7}, {%8,%9}, {%0,%1,%2,%3};"
                : "+f"(a0), "+f"(a1), "+f"(a2), "+f"(a3)
                : "r"(av.x), "r"(av.y), "r"(av.z), "r"(av.w),
                  "r"(bv.x), "r"(bv.y));
        }

        // c0:(row g, col 2tig) c1:(g, 2tig+1) c2:(g+8, 2tig) c3:(g+8, 2tig+1)
        const int g = l >> 2, tig = l & 3;
        const int o = nt * 8 + tig * 2;
        float b0 = __ldg(&db[o]), b1 = __ldg(&db[o + 1]);
        size_t base = ((size_t)(b * CO + o) * Hh + h) * Ww + w0;
        out[base + g]               = a0 + b0;
        out[base + Hh * Ww + g]     = a1 + b1;
        out[base + g + 8]           = a2 + b0;
        out[base + Hh * Ww + g + 8] = a3 + b1;
    }
}

extern "C" void kernel_launch(void* const* d_in, const int* in_sizes, int n_in,
                              void* d_out, int out_size)
{
    const float* x   = (const float*)d_in[0];   // [8,64,128,128]
    const float* ow  = (const float*)d_in[1];   // [1152,1,3,3]
    const float* obv = (const float*)d_in[2];   // [1152]
    const float* dw  = (const float*)d_in[3];   // [64,64,3,3]
    const float* db  = (const float*)d_in[4];   // [64]
    float* out = (float*)d_out;                 // [8,64,128,128]

    cudaFuncSetAttribute(deform_fused_kernel,
                         cudaFuncAttributeMaxDynamicSharedMemorySize, SMEM_BYTES);

    prep_kernel<<<144, 256>>>(dw, ow, obv);

    dim3 grid(Ww / Pp, Hh, Bq);   // (8, 128, 8) = 8192 CTAs
    deform_fused_kernel<<<grid, 256, SMEM_BYTES>>>(x, db, out);
}

// round 14
// speedup vs baseline: 4.5615x; 1.1904x over previous
#include <cuda_runtime.h>
#include <cuda_fp16.h>
#include <cstdint>

// DeformableConv2d v10, sm_103a.
// v9b (375us) with the GEMM switched tf32 -> fp16 (m16n8k16):
//  - fp16 keeps tf32's 10 mantissa bits; values are O(1) -> no range issues
//  - saf 36.9->18.4KB => smem 57.9KB, L1D recovers to ~54KB (g_sow resident)
//  - B fragment stream halves (147->73.7KB per CTA), mainloop halves to 36 steps
// K = 576 = 36*16 exactly, no padding.

#define Bq 8
#define Cc 64
#define Hh 128
#define Ww 128
#define CO 64
#define Pp 16

// smem layout (float slots)
#define U_F     0        // union: patch [64][4][20]=5120  /  safH 4608
#define EA_F    5120     // exp(e) __half2: [64 c][18 j][8 h2] = 9216 slots
#define RED_F   14336    // [8][16] = 128
#define INVS_F  14464    // [16]
#define SM_TOTAL 14480
#define SMEM_BYTES (SM_TOTAL*4)      // 57,920 B -> 3 CTAs/SM, L1D ~54KB

__device__ uint32_t g_bfragH[8 * 36 * 32 * 2];  // [ntile][kb][lane][2] f16x2
__device__ float    g_sow[64 * 18 * 12];        // per (c,j): {w[9],bias,pad,pad}

__global__ void prep_kernel(const float* __restrict__ dw,
                            const float* __restrict__ ow,
                            const float* __restrict__ obv)
{
    int i = blockIdx.x * 256 + threadIdx.x;
    if (i < 8 * 36 * 64) {
        int nt  = i / (36 * 64);
        int rem = i - nt * 36 * 64;
        int kb  = rem >> 6;
        int le  = rem & 63;
        int lane = le >> 1, ii = le & 1;        // ii = b-reg (rows +8*ii)
        int g = lane >> 2, tig = lane & 3;
        int o   = nt * 8 + g;
        int ck0 = kb * 16 + 2 * tig + ii * 8;   // <= 575
        __half2 hv = __floats2half2_rn(dw[o * 576 + ck0], dw[o * 576 + ck0 + 1]);
        g_bfragH[i] = *(uint32_t*)&hv;
    }
    if (i < 64 * 18 * 12) {
        int cj = i / 12, m = i - cj * 12;
        float v = 0.0f;
        if (m < 9) v = ow[cj * 9 + m]; else if (m == 9) v = obv[cj];
        g_sow[i] = v;
    }
}

__device__ __forceinline__ void load_w9(const float* wc, int j,
                                        float w9[9], float& bias)
{
    float4 a = __ldg((const float4*)(wc + j * 12 + 0));
    float4 b = __ldg((const float4*)(wc + j * 12 + 4));
    float4 c = __ldg((const float4*)(wc + j * 12 + 8));
    w9[0]=a.x; w9[1]=a.y; w9[2]=a.z; w9[3]=a.w;
    w9[4]=b.x; w9[5]=b.y; w9[6]=b.z; w9[7]=b.w; w9[8]=c.x; bias=c.y;
}

__global__ __launch_bounds__(256, 3)
void deform_fused_kernel(const float* __restrict__ x,
                         const float* __restrict__ db,
                         float* __restrict__ out)
{
    extern __shared__ float sm[];
    float*   patch = sm + U_F;                 // phase 1 .. pass B pv load
    __half*  safH  = (__half*)(sm + U_F);      // pass B .. GEMM (overlay)
    __half2* eah   = (__half2*)(sm + EA_F);    // exp cache [c][j][8 h2]
    float*   red   = sm + RED_F;
    float*   invS  = sm + INVS_F;

    const int t  = threadIdx.x;
    const int w0 = blockIdx.x * Pp;
    const int h  = blockIdx.y;
    const int b  = blockIdx.z;

    // ---- Phase 1: load 4x20 zero-padded x patch per channel ----
    {
        const float* xb = x + (size_t)b * Cc * Hh * Ww;
        for (int i = t; i < 5120; i += 256) {
            int c   = i / 80;
            int r2  = i - c * 80;
            int r   = r2 / 20;
            int col = r2 - r * 20;
            int gy = h - 1 + r;
            int gx = w0 - 1 + col;
            float v = 0.0f;
            if (gy >= 0 && gy < Hh && gx >= 0 && gx < Ww)
                v = xb[(size_t)c * (Hh * Ww) + gy * Ww + gx];
            patch[i] = v;
        }
    }
    __syncthreads();

    const int c  = t >> 2;
    const int pA = (t & 3) * 4;
    const float* wc = g_sow + c * 216;

    // ---- Pass A: conv -> exp -> cache exp (__half2) + per-position sums ----
    float sums[4] = {0.f, 0.f, 0.f, 0.f};
    {
        float pv3[3][6];
        #pragma unroll
        for (int r = 0; r < 3; r++)
            #pragma unroll
            for (int s = 0; s < 6; s++)
                pv3[r][s] = patch[(c * 4 + r) * 20 + pA + s];

        #pragma unroll
        for (int j = 0; j < 18; j++) {
            float w9[9], bias;
            load_w9(wc, j, w9, bias);
            float e[4] = {bias, bias, bias, bias};
            #pragma unroll
            for (int r = 0; r < 3; r++)
                #pragma unroll
                for (int s = 0; s < 3; s++) {
                    float wv = w9[r * 3 + s];
                    #pragma unroll
                    for (int q = 0; q < 4; q++)
                        e[q] += wv * pv3[r][s + q];
                }
            float x0 = __expf(e[0]), x1 = __expf(e[1]);
            float x2 = __expf(e[2]), x3 = __expf(e[3]);
            sums[0] += x0; sums[1] += x1; sums[2] += x2; sums[3] += x3;
            __half2* dst = &eah[(c * 18 + j) * 8 + (pA >> 1)];
            dst[0] = __floats2half2_rn(x0, x1);
            dst[1] = __floats2half2_rn(x2, x3);
        }
    }
    #pragma unroll
    for (int off = 4; off <= 16; off <<= 1)
        #pragma unroll
        for (int q = 0; q < 4; q++)
            sums[q] += __shfl_xor_sync(0xffffffffu, sums[q], off);
    {
        int lane = t & 31, warp = t >> 5;
        if (lane < 4) {
            #pragma unroll
            for (int q = 0; q < 4; q++)
                red[warp * 16 + lane * 4 + q] = sums[q];
        }
    }
    __syncthreads();
    if (t < 16) {
        float s = 0.f;
        #pragma unroll
        for (int w = 0; w < 8; w++) s += red[w * 16 + t];
        invS[t] = 1.0f / s;
    }
    __syncthreads();

    float4 iv4 = *(const float4*)&invS[pA];
    float iv[4] = {iv4.x, iv4.y, iv4.z, iv4.w};

    // ---- Pass B: read cached exp, bilinear -> A fragments (f16) ----
    {
        float pv[4][7];
        #pragma unroll
        for (int r = 0; r < 4; r++)
            #pragma unroll
            for (int s = 0; s < 7; s++)
                pv[r][s] = patch[(c * 4 + r) * 20 + pA + s];
        __syncthreads();     // all pv loaded before safH overlays patch

        #pragma unroll
        for (int k = 0; k < 9; k++) {
            const int ky = k / 3, kx = k % 3;
            const int ck  = c * 9 + k;
            const int kb  = ck >> 4;
            const int c16 = ck & 15;
            const int tig   = (c16 & 7) >> 1;
            const int halfk = c16 >> 3;
            const int hsel  = c16 & 1;

            const __half2* py = &eah[(c * 18 + 2 * k)     * 8 + (pA >> 1)];
            const __half2* px = &eah[(c * 18 + 2 * k + 1) * 8 + (pA >> 1)];
            float2 y01 = __half22float2(py[0]);
            float2 y23 = __half22float2(py[1]);
            float2 x01 = __half22float2(px[0]);
            float2 x23 = __half22float2(px[1]);
            float eyv[4] = {y01.x, y01.y, y23.x, y23.y};
            float exv[4] = {x01.x, x01.y, x23.x, x23.y};

            #pragma unroll
            for (int q = 0; q < 4; q++) {
                float dy = eyv[q] * iv[q];
                float dx = exv[q] * iv[q];
                float a00 = pv[ky][q + kx],     a01 = pv[ky][q + kx + 1];
                float a10 = pv[ky + 1][q + kx], a11 = pv[ky + 1][q + kx + 1];
                float top = a00 + dx * (a01 - a00);
                float bot = a10 + dx * (a11 - a10);
                float res = top + dy * (bot - top);
                int p = pA + q;
                int lane = (p & 7) * 4 + tig;
                int reg  = halfk * 2 + (p >> 3);
                safH[((kb * 32 + lane) << 3) + (reg << 1) + hsel] =
                    __float2half_rn(res);
            }
        }
    }
    __syncthreads();

    // ---- Phase 5: mma.sync f16 m16n8k16. Warp w = n-tile w; 36 k-steps ----
    {
        const int nt = t >> 5;
        const int l  = t & 31;
        float a0 = 0.f, a1 = 0.f, a2 = 0.f, a3 = 0.f;
        const uint32_t* bp = g_bfragH + nt * (36 * 64) + l * 2;
        const uint32_t* ap = (const uint32_t*)safH + l * 4;

        #pragma unroll 6
        for (int kb = 0; kb < 36; kb++) {
            uint4 av = *(const uint4*)(ap + kb * 128);
            uint2 bv = __ldg((const uint2*)(bp + kb * 64));
            asm("mma.sync.aligned.m16n8k16.row.col.f32.f16.f16.f32 "
                "{%0,%1,%2,%3}, {%4,%5,%6,%7}, {%8,%9}, {%0,%1,%2,%3};"
                : "+f"(a0), "+f"(a1), "+f"(a2), "+f"(a3)
                : "r"(av.x), "r"(av.y), "r"(av.z), "r"(av.w),
                  "r"(bv.x), "r"(bv.y));
        }

        // c0:(row g, col 2tig) c1:(g, 2tig+1) c2:(g+8, 2tig) c3:(g+8, 2tig+1)
        const int g = l >> 2, tig = l & 3;
        const int o = nt * 8 + tig * 2;
        float b0 = __ldg(&db[o]), b1 = __ldg(&db[o + 1]);
        size_t base = ((size_t)(b * CO + o) * Hh + h) * Ww + w0;
        out[base + g]               = a0 + b0;
        out[base + Hh * Ww + g]     = a1 + b1;
        out[base + g + 8]           = a2 + b0;
        out[base + Hh * Ww + g + 8] = a3 + b1;
    }
}

extern "C" void kernel_launch(void* const* d_in, const int* in_sizes, int n_in,
                              void* d_out, int out_size)
{
    const float* x   = (const float*)d_in[0];   // [8,64,128,128]
    const float* ow  = (const float*)d_in[1];   // [1152,1,3,3]
    const float* obv = (const float*)d_in[2];   // [1152]
    const float* dw  = (const float*)d_in[3];   // [64,64,3,3]
    const float* db  = (const float*)d_in[4];   // [64]
    float* out = (float*)d_out;                 // [8,64,128,128]

    cudaFuncSetAttribute(deform_fused_kernel,
                         cudaFuncAttributeMaxDynamicSharedMemorySize, SMEM_BYTES);

    prep_kernel<<<72, 256>>>(dw, ow, obv);

    dim3 grid(Ww / Pp, Hh, Bq);   // (8, 128, 8) = 8192 CTAs
    deform_fused_kernel<<<grid, 256, SMEM_BYTES>>>(x, db, out);
}

// round 15
// speedup vs baseline: 5.4380x; 1.1922x over previous
#include <cuda_runtime.h>
#include <cuda_fp16.h>
#include <cstdint>

// DeformableConv2d v11, sm_103a.
// v10 (315us) with the offset conv done in half2, pairing each tap's
// (dy, dx) offset channels in the two fp16 lanes:
//  - conv: 648 FFMA -> 324 HFMA2; weight table pre-paired -> LDG 54->27
//  - eah relaid [c][9k][16p] as (ey,ex) half2 -> STS 36->9 (.128), LDS 18->9
// GEMM unchanged: mma.sync m16n8k16 f16, K=576=36*16.

#define Bq 8
#define Cc 64
#define Hh 128
#define Ww 128
#define CO 64
#define Pp 16

// smem layout (float slots)
#define U_F     0        // union: patch [64][4][20]=5120  /  safH 4608
#define EA_F    5120     // exp pairs __half2: [64 c][9 k][16 p] = 9216 h2
#define RED_F   14336    // [8][16] = 128
#define INVS_F  14464    // [16]
#define SM_TOTAL 14480
#define SMEM_BYTES (SM_TOTAL*4)      // 57,920 B -> 3 CTAs/SM

__device__ uint32_t g_bfragH[8 * 36 * 32 * 2];  // [ntile][kb][lane][2] f16x2
__device__ uint32_t g_sowH[64 * 9 * 12];        // per (c,k): {(wy,wx)[9],(by,bx),pad,pad}

__device__ __forceinline__ __half2 u2h(uint32_t u) { __half2 h; *(uint32_t*)&h = u; return h; }
__device__ __forceinline__ uint32_t h2u(__half2 h) { return *(uint32_t*)&h; }

__global__ void prep_kernel(const float* __restrict__ dw,
                            const float* __restrict__ ow,
                            const float* __restrict__ obv)
{
    int i = blockIdx.x * 256 + threadIdx.x;
    if (i < 8 * 36 * 64) {
        int nt  = i / (36 * 64);
        int rem = i - nt * 36 * 64;
        int kb  = rem >> 6;
        int le  = rem & 63;
        int lane = le >> 1, ii = le & 1;        // ii = b-reg (rows +8*ii)
        int g = lane >> 2, tig = lane & 3;
        int o   = nt * 8 + g;
        int ck0 = kb * 16 + 2 * tig + ii * 8;
        __half2 hv = __floats2half2_rn(dw[o * 576 + ck0], dw[o * 576 + ck0 + 1]);
        g_bfragH[i] = h2u(hv);
    }
    if (i < 64 * 9 * 12) {
        int ck = i / 12, m = i - ck * 12;
        int c = ck / 9, k = ck - c * 9;
        int jy = c * 18 + 2 * k;                // dy channel
        float vy = 0.f, vx = 0.f;
        if (m < 9)       { vy = ow[jy * 9 + m]; vx = ow[(jy + 1) * 9 + m]; }
        else if (m == 9) { vy = obv[jy];        vx = obv[jy + 1]; }
        g_sowH[i] = h2u(__floats2half2_rn(vy, vx));
    }
}

__global__ __launch_bounds__(256, 3)
void deform_fused_kernel(const float* __restrict__ x,
                         const float* __restrict__ db,
                         float* __restrict__ out)
{
    extern __shared__ float sm[];
    float*   patch = sm + U_F;                 // phase 1 .. pass B pv load
    __half*  safH  = (__half*)(sm + U_F);      // pass B .. GEMM (overlay)
    __half2* eah   = (__half2*)(sm + EA_F);    // exp pairs [c][k][16 p]
    float*   red   = sm + RED_F;
    float*   invS  = sm + INVS_F;

    const int t  = threadIdx.x;
    const int w0 = blockIdx.x * Pp;
    const int h  = blockIdx.y;
    const int b  = blockIdx.z;

    // ---- Phase 1: load 4x20 zero-padded x patch per channel ----
    {
        const float* xb = x + (size_t)b * Cc * Hh * Ww;
        for (int i = t; i < 5120; i += 256) {
            int c   = i / 80;
            int r2  = i - c * 80;
            int r   = r2 / 20;
            int col = r2 - r * 20;
            int gy = h - 1 + r;
            int gx = w0 - 1 + col;
            float v = 0.0f;
            if (gy >= 0 && gy < Hh && gx >= 0 && gx < Ww)
                v = xb[(size_t)c * (Hh * Ww) + gy * Ww + gx];
            patch[i] = v;
        }
    }
    __syncthreads();

    const int c  = t >> 2;
    const int pA = (t & 3) * 4;

    // ---- Pass A: half2 conv (lanes = dy,dx channels) -> exp pairs ----
    float sums[4] = {0.f, 0.f, 0.f, 0.f};
    {
        __half2 sp[3][6];
        #pragma unroll
        for (int r = 0; r < 3; r++)
            #pragma unroll
            for (int s = 0; s < 6; s++)
                sp[r][s] = __float2half2_rn(patch[(c * 4 + r) * 20 + pA + s]);

        const uint32_t* wcH = g_sowH + c * 108;
        #pragma unroll
        for (int k = 0; k < 9; k++) {
            uint4 wa = __ldg((const uint4*)(wcH + k * 12));
            uint4 wb = __ldg((const uint4*)(wcH + k * 12 + 4));
            uint2 wz = __ldg((const uint2*)(wcH + k * 12 + 8));
            __half2 w2[9] = {u2h(wa.x), u2h(wa.y), u2h(wa.z), u2h(wa.w),
                             u2h(wb.x), u2h(wb.y), u2h(wb.z), u2h(wb.w),
                             u2h(wz.x)};
            __half2 b2 = u2h(wz.y);
            __half2 e[4] = {b2, b2, b2, b2};
            #pragma unroll
            for (int r = 0; r < 3; r++)
                #pragma unroll
                for (int s = 0; s < 3; s++) {
                    __half2 wv = w2[r * 3 + s];
                    #pragma unroll
                    for (int q = 0; q < 4; q++)
                        e[q] = __hfma2(wv, sp[r][s + q], e[q]);
                }
            uint32_t ou[4];
            #pragma unroll
            for (int q = 0; q < 4; q++) {
                float2 ef = __half22float2(e[q]);
                float ey = __expf(ef.x);
                float ex = __expf(ef.y);
                sums[q] += ey + ex;
                ou[q] = h2u(__floats2half2_rn(ey, ex));
            }
            *(uint4*)&eah[(c * 9 + k) * 16 + pA] =
                make_uint4(ou[0], ou[1], ou[2], ou[3]);
        }
    }
    #pragma unroll
    for (int off = 4; off <= 16; off <<= 1)
        #pragma unroll
        for (int q = 0; q < 4; q++)
            sums[q] += __shfl_xor_sync(0xffffffffu, sums[q], off);
    {
        int lane = t & 31, warp = t >> 5;
        if (lane < 4) {
            #pragma unroll
            for (int q = 0; q < 4; q++)
                red[warp * 16 + lane * 4 + q] = sums[q];
        }
    }
    __syncthreads();
    if (t < 16) {
        float s = 0.f;
        #pragma unroll
        for (int w = 0; w < 8; w++) s += red[w * 16 + t];
        invS[t] = 1.0f / s;
    }
    __syncthreads();

    float4 iv4 = *(const float4*)&invS[pA];
    float iv[4] = {iv4.x, iv4.y, iv4.z, iv4.w};

    // ---- Pass B: read exp pairs, bilinear -> A fragments (f16) ----
    {
        float pv[4][7];
        #pragma unroll
        for (int r = 0; r < 4; r++)
            #pragma unroll
            for (int s = 0; s < 7; s++)
                pv[r][s] = patch[(c * 4 + r) * 20 + pA + s];
        __syncthreads();     // all pv loaded before safH overlays patch

        #pragma unroll
        for (int k = 0; k < 9; k++) {
            const int ky = k / 3, kx = k % 3;
            const int ck  = c * 9 + k;
            const int kb  = ck >> 4;
            const int c16 = ck & 15;
            const int tig   = (c16 & 7) >> 1;
            const int halfk = c16 >> 3;
            const int hsel  = c16 & 1;

            uint4 ev = *(const uint4*)&eah[(c * 9 + k) * 16 + pA];
            uint32_t eu[4] = {ev.x, ev.y, ev.z, ev.w};

            #pragma unroll
            for (int q = 0; q < 4; q++) {
                float2 ef = __half22float2(u2h(eu[q]));
                float dy = ef.x * iv[q];
                float dx = ef.y * iv[q];
                float a00 = pv[ky][q + kx],     a01 = pv[ky][q + kx + 1];
                float a10 = pv[ky + 1][q + kx], a11 = pv[ky + 1][q + kx + 1];
                float top = a00 + dx * (a01 - a00);
                float bot = a10 + dx * (a11 - a10);
                float res = top + dy * (bot - top);
                int p = pA + q;
                int lane = (p & 7) * 4 + tig;
                int reg  = halfk * 2 + (p >> 3);
                safH[((kb * 32 + lane) << 3) + (reg << 1) + hsel] =
                    __float2half_rn(res);
            }
        }
    }
    __syncthreads();

    // ---- Phase 5: mma.sync f16 m16n8k16. Warp w = n-tile w; 36 k-steps ----
    {
        const int nt = t >> 5;
        const int l  = t & 31;
        float a0 = 0.f, a1 = 0.f, a2 = 0.f, a3 = 0.f;
        const uint32_t* bp = g_bfragH + nt * (36 * 64) + l * 2;
        const uint32_t* ap = (const uint32_t*)safH + l * 4;

        #pragma unroll 6
        for (int kb = 0; kb < 36; kb++) {
            uint4 av = *(const uint4*)(ap + kb * 128);
            uint2 bv = __ldg((const uint2*)(bp + kb * 64));
            asm("mma.sync.aligned.m16n8k16.row.col.f32.f16.f16.f32 "
                "{%0,%1,%2,%3}, {%4,%5,%6,%7}, {%8,%9}, {%0,%1,%2,%3};"
                : "+f"(a0), "+f"(a1), "+f"(a2), "+f"(a3)
                : "r"(av.x), "r"(av.y), "r"(av.z), "r"(av.w),
                  "r"(bv.x), "r"(bv.y));
        }

        // c0:(row g, col 2tig) c1:(g, 2tig+1) c2:(g+8, 2tig) c3:(g+8, 2tig+1)
        const int g = l >> 2, tig = l & 3;
        const int o = nt * 8 + tig * 2;
        float b0 = __ldg(&db[o]), b1 = __ldg(&db[o + 1]);
        size_t base = ((size_t)(b * CO + o) * Hh + h) * Ww + w0;
        out[base + g]               = a0 + b0;
        out[base + Hh * Ww + g]     = a1 + b1;
        out[base + g + 8]           = a2 + b0;
        out[base + Hh * Ww + g + 8] = a3 + b1;
    }
}

extern "C" void kernel_launch(void* const* d_in, const int* in_sizes, int n_in,
                              void* d_out, int out_size)
{
    const float* x   = (const float*)d_in[0];   // [8,64,128,128]
    const float* ow  = (const float*)d_in[1];   // [1152,1,3,3]
    const float* obv = (const float*)d_in[2];   // [1152]
    const float* dw  = (const float*)d_in[3];   // [64,64,3,3]
    const float* db  = (const float*)d_in[4];   // [64]
    float* out = (float*)d_out;                 // [8,64,128,128]

    cudaFuncSetAttribute(deform_fused_kernel,
                         cudaFuncAttributeMaxDynamicSharedMemorySize, SMEM_BYTES);

    prep_kernel<<<72, 256>>>(dw, ow, obv);

    dim3 grid(Ww / Pp, Hh, Bq);   // (8, 128, 8) = 8192 CTAs
    deform_fused_kernel<<<grid, 256, SMEM_BYTES>>>(x, db, out);
}

// round 16
// speedup vs baseline: 6.0553x; 1.1135x over previous
#include <cuda_runtime.h>
#include <cuda_fp16.h>
#include <cstdint>

// DeformableConv2d v12, sm_103a.
// Softmax-linearization split-GEMM:
//   res = a00 + iv_p * L,   L = ex*(a01-a00) + ey*(a10-a00)
// (iv = 1/softmax-denominator ~ 1e-3; the iv^2*ey*ex cross term is <=2.4e-5
//  absolute and dropped). Since MMA is linear and iv is constant per A-row:
//   OUT = A0*B + diag(iv)*(AL*B)  -> two mma passes sharing B fragments,
// iv applied in the epilogue. Pass B is gone; pass A emits both A-fragment
// sets directly. smem 39.5KB -> 4 CTAs/SM.

#define Bq 8
#define Cc 64
#define Hh 128
#define Ww 128
#define CO 64
#define Pp 16

// smem layout (float slots)
#define U_F     0        // union: patch [64][4][20]=5120  /  saf0 (4608 u32)
#define SAFL_F  5120     // safL 4608 u32
#define RED_F   9728     // [8][16] = 128
#define INVS_F  9856     // [16]
#define SM_TOTAL 9872
#define SMEM_BYTES (SM_TOTAL*4)      // 39,488 B -> 4 CTAs/SM

__device__ uint32_t g_bfragH[8 * 36 * 32 * 2];  // [ntile][kb][lane][2] f16x2
__device__ uint32_t g_sowH[64 * 9 * 12];        // per (c,k): {(wy,wx)[9],(by,bx),pad,pad}

__device__ __forceinline__ __half2 u2h(uint32_t u) { __half2 h; *(uint32_t*)&h = u; return h; }
__device__ __forceinline__ uint32_t h2u(__half2 h) { return *(uint32_t*)&h; }

__global__ void prep_kernel(const float* __restrict__ dw,
                            const float* __restrict__ ow,
                            const float* __restrict__ obv)
{
    int i = blockIdx.x * 256 + threadIdx.x;
    if (i < 8 * 36 * 64) {
        int nt  = i / (36 * 64);
        int rem = i - nt * 36 * 64;
        int kb  = rem >> 6;
        int le  = rem & 63;
        int lane = le >> 1, ii = le & 1;
        int g = lane >> 2, tig = lane & 3;
        int o   = nt * 8 + g;
        int ck0 = kb * 16 + 2 * tig + ii * 8;
        g_bfragH[i] = h2u(__floats2half2_rn(dw[o * 576 + ck0], dw[o * 576 + ck0 + 1]));
    }
    if (i < 64 * 9 * 12) {
        int ck = i / 12, m = i - ck * 12;
        int c = ck / 9, k = ck - c * 9;
        int jy = c * 18 + 2 * k;
        float vy = 0.f, vx = 0.f;
        if (m < 9)       { vy = ow[jy * 9 + m]; vx = ow[(jy + 1) * 9 + m]; }
        else if (m == 9) { vy = obv[jy];        vx = obv[jy + 1]; }
        g_sowH[i] = h2u(__floats2half2_rn(vy, vx));
    }
}

__global__ __launch_bounds__(256, 4)
void deform_fused_kernel(const float* __restrict__ x,
                         const float* __restrict__ db,
                         float* __restrict__ out)
{
    extern __shared__ float sm[];
    float*  patch = sm + U_F;
    __half* saf0H = (__half*)(sm + U_F);       // overlays patch after sp load
    __half* safLH = (__half*)(sm + SAFL_F);
    float*  red   = sm + RED_F;
    float*  invS  = sm + INVS_F;

    const int t  = threadIdx.x;
    const int w0 = blockIdx.x * Pp;
    const int h  = blockIdx.y;
    const int b  = blockIdx.z;

    // ---- Phase 1: load 4x20 zero-padded x patch per channel ----
    {
        const float* xb = x + (size_t)b * Cc * Hh * Ww;
        for (int i = t; i < 5120; i += 256) {
            int c   = i / 80;
            int r2  = i - c * 80;
            int r   = r2 / 20;
            int col = r2 - r * 20;
            int gy = h - 1 + r;
            int gx = w0 - 1 + col;
            float v = 0.0f;
            if (gy >= 0 && gy < Hh && gx >= 0 && gx < Ww)
                v = xb[(size_t)c * (Hh * Ww) + gy * Ww + gx];
            patch[i] = v;
        }
    }
    __syncthreads();

    const int c  = t >> 2;
    const int pA = (t & 3) * 4;

    // sp: splatted half2 patch regs, rows 0..3, cols 0..6
    __half2 sp[4][7];
    #pragma unroll
    for (int r = 0; r < 4; r++)
        #pragma unroll
        for (int s = 0; s < 7; s++)
            sp[r][s] = __float2half2_rn(patch[(c * 4 + r) * 20 + pA + s]);
    __syncthreads();      // patch dead -> saf0 may overlay

    // ---- Pass A: half2 conv -> h2exp -> sums + A0/AL fragments ----
    float sums[4] = {0.f, 0.f, 0.f, 0.f};
    {
        const uint32_t* wcH = g_sowH + c * 108;
        #pragma unroll
        for (int k = 0; k < 9; k++) {
            uint4 wa = __ldg((const uint4*)(wcH + k * 12));
            uint4 wb = __ldg((const uint4*)(wcH + k * 12 + 4));
            uint2 wz = __ldg((const uint2*)(wcH + k * 12 + 8));
            __half2 w2[9] = {u2h(wa.x), u2h(wa.y), u2h(wa.z), u2h(wa.w),
                             u2h(wb.x), u2h(wb.y), u2h(wb.z), u2h(wb.w),
                             u2h(wz.x)};
            __half2 b2 = u2h(wz.y);
            __half2 e[4] = {b2, b2, b2, b2};
            #pragma unroll
            for (int r = 0; r < 3; r++)
                #pragma unroll
                for (int s = 0; s < 3; s++) {
                    __half2 wv = w2[r * 3 + s];
                    #pragma unroll
                    for (int q = 0; q < 4; q++)
                        e[q] = __hfma2(wv, sp[r][s + q], e[q]);
                }

            const int ky = k / 3, kx = k % 3;
            const int ck  = c * 9 + k;
            const int kb  = ck >> 4;
            const int c16 = ck & 15;
            const int tig   = (c16 & 7) >> 1;
            const int halfk = c16 >> 3;
            const int hsel  = c16 & 1;

            #pragma unroll
            for (int q = 0; q < 4; q++) {
                __half2 ee = h2exp(e[q]);          // (ey_exp, ex_exp)
                float2 ef = __half22float2(ee);
                sums[q] += ef.x + ef.y;
                __half a00 = __low2half(sp[ky][kx + q]);
                __half dh  = __low2half(__hsub2(sp[ky][kx + q + 1], sp[ky][kx + q]));
                __half dv  = __low2half(__hsub2(sp[ky + 1][kx + q], sp[ky][kx + q]));
                __half L   = __hfma(__high2half(ee), dh,
                                    __hmul(__low2half(ee), dv));
                int p = pA + q;
                int lane = (p & 7) * 4 + tig;
                int reg  = halfk * 2 + (p >> 3);
                int idx  = ((kb * 32 + lane) << 3) + (reg << 1) + hsel;
                saf0H[idx] = a00;
                safLH[idx] = L;
            }
        }
    }
    // ---- softmax denominator reduction ----
    #pragma unroll
    for (int off = 4; off <= 16; off <<= 1)
        #pragma unroll
        for (int q = 0; q < 4; q++)
            sums[q] += __shfl_xor_sync(0xffffffffu, sums[q], off);
    {
        int lane = t & 31, warp = t >> 5;
        if (lane < 4) {
            #pragma unroll
            for (int q = 0; q < 4; q++)
                red[warp * 16 + lane * 4 + q] = sums[q];
        }
    }
    __syncthreads();
    if (t < 16) {
        float s = 0.f;
        #pragma unroll
        for (int w = 0; w < 8; w++) s += red[w * 16 + t];
        invS[t] = 1.0f / s;
    }
    __syncthreads();

    // ---- Split GEMM: D = A0*B, DL = AL*B (shared B); 36 k-steps ----
    {
        const int nt = t >> 5;
        const int l  = t & 31;
        float d0 = 0.f, d1 = 0.f, d2 = 0.f, d3 = 0.f;
        float l0 = 0.f, l1 = 0.f, l2 = 0.f, l3 = 0.f;
        const uint32_t* bp  = g_bfragH + nt * (36 * 64) + l * 2;
        const uint32_t* a0p = (const uint32_t*)saf0H + l * 4;
        const uint32_t* aLp = (const uint32_t*)safLH + l * 4;

        #pragma unroll 4
        for (int kb = 0; kb < 36; kb++) {
            uint4 av0 = *(const uint4*)(a0p + kb * 128);
            uint4 avL = *(const uint4*)(aLp + kb * 128);
            uint2 bv  = __ldg((const uint2*)(bp + kb * 64));
            asm("mma.sync.aligned.m16n8k16.row.col.f32.f16.f16.f32 "
                "{%0,%1,%2,%3}, {%4,%5,%6,%7}, {%8,%9}, {%0,%1,%2,%3};"
                : "+f"(d0), "+f"(d1), "+f"(d2), "+f"(d3)
                : "r"(av0.x), "r"(av0.y), "r"(av0.z), "r"(av0.w),
                  "r"(bv.x), "r"(bv.y));
            asm("mma.sync.aligned.m16n8k16.row.col.f32.f16.f16.f32 "
                "{%0,%1,%2,%3}, {%4,%5,%6,%7}, {%8,%9}, {%0,%1,%2,%3};"
                : "+f"(l0), "+f"(l1), "+f"(l2), "+f"(l3)
                : "r"(avL.x), "r"(avL.y), "r"(avL.z), "r"(avL.w),
                  "r"(bv.x), "r"(bv.y));
        }

        // c0:(row g, col 2tig) c1:(g, 2tig+1) c2:(g+8, 2tig) c3:(g+8, 2tig+1)
        const int g = l >> 2, tig = l & 3;
        const int o = nt * 8 + tig * 2;
        float bb0 = __ldg(&db[o]), bb1 = __ldg(&db[o + 1]);
        float ivg  = invS[g];
        float ivg8 = invS[g + 8];
        size_t base = ((size_t)(b * CO + o) * Hh + h) * Ww + w0;
        out[base + g]               = d0 + ivg  * l0 + bb0;
        out[base + Hh * Ww + g]     = d1 + ivg  * l1 + bb1;
        out[base + g + 8]           = d2 + ivg8 * l2 + bb0;
        out[base + Hh * Ww + g + 8] = d3 + ivg8 * l3 + bb1;
    }
}

extern "C" void kernel_launch(void* const* d_in, const int* in_sizes, int n_in,
                              void* d_out, int out_size)
{
    const float* x   = (const float*)d_in[0];   // [8,64,128,128]
    const float* ow  = (const float*)d_in[1];   // [1152,1,3,3]
    const float* obv = (const float*)d_in[2];   // [1152]
    const float* dw  = (const float*)d_in[3];   // [64,64,3,3]
    const float* db  = (const float*)d_in[4];   // [64]
    float* out = (float*)d_out;                 // [8,64,128,128]

    cudaFuncSetAttribute(deform_fused_kernel,
                         cudaFuncAttributeMaxDynamicSharedMemorySize, SMEM_BYTES);

    prep_kernel<<<72, 256>>>(dw, ow, obv);

    dim3 grid(Ww / Pp, Hh, Bq);   // (8, 128, 8) = 8192 CTAs
    deform_fused_kernel<<<grid, 256, SMEM_BYTES>>>(x, db, out);
}

// round 17
// speedup vs baseline: 6.6766x; 1.1026x over previous
#include <cuda_runtime.h>
#include <cuda_fp16.h>
#include <cstdint>

// DeformableConv2d v13, sm_103a.
// v12 (237.6us) instruction diet:
//  - patch smem round trip deleted: 28 predicated LDG.32 direct from x
//  - K' permutation (channel-pair blocks [c0 k0-7 | c1 k0-7 | c0k8,c1k8])
//    makes every thread's fragment stores pairable -> STS.32, uniform code
//  - B prep uses the same permutation (exact)
// Split-GEMM (OUT = A0*B + diag(iv)*(AL*B)) unchanged, mma m16n8k16 f16.

#define Bq 8
#define Cc 64
#define Hh 128
#define Ww 128
#define CO 64
#define Pp 16

// smem layout (float slots)
#define SAF0_F 0        // A0 fragments: 4608 u32
#define SAFL_F 4608     // AL fragments: 4608 u32
#define RED_F  9216     // [8][16] = 128
#define INVS_F 9344     // [16]
#define SM_TOTAL 9360
#define SMEM_BYTES (SM_TOTAL*4)      // 37,440 B -> 4 CTAs/SM (reg-capped too)

__device__ uint32_t g_bfragH[8 * 36 * 32 * 2];  // [ntile][kb][lane][2] f16x2
__device__ uint32_t g_sowH[64 * 9 * 12];        // per (c,k): {(wy,wx)[9],(by,bx),pad,pad}

__device__ __forceinline__ __half2 u2h(uint32_t u) { __half2 h; *(uint32_t*)&h = u; return h; }
__device__ __forceinline__ uint32_t h2u(__half2 h) { return *(uint32_t*)&h; }

// K' -> original ck.  K' blocks of 18 per channel pair:
// [c_even k0..7 | c_odd k0..7 | c_even k8, c_odd k8]
__device__ __forceinline__ int orig_ck(int ckp)
{
    int cp  = ckp / 18;
    int rem = ckp - 18 * cp;
    int c, k;
    if (rem < 8)       { c = 2 * cp;             k = rem; }
    else if (rem < 16) { c = 2 * cp + 1;         k = rem - 8; }
    else               { c = 2 * cp + (rem - 16); k = 8; }
    return c * 9 + k;
}

__global__ void prep_kernel(const float* __restrict__ dw,
                            const float* __restrict__ ow,
                            const float* __restrict__ obv)
{
    int i = blockIdx.x * 256 + threadIdx.x;
    if (i < 8 * 36 * 64) {
        int nt  = i / (36 * 64);
        int rem = i - nt * 36 * 64;
        int kb  = rem >> 6;
        int le  = rem & 63;
        int lane = le >> 1, ii = le & 1;
        int g = lane >> 2, tig = lane & 3;
        int o    = nt * 8 + g;
        int ckp0 = kb * 16 + 2 * tig + ii * 8;
        g_bfragH[i] = h2u(__floats2half2_rn(dw[o * 576 + orig_ck(ckp0)],
                                            dw[o * 576 + orig_ck(ckp0 + 1)]));
    }
    if (i < 64 * 9 * 12) {
        int ck = i / 12, m = i - ck * 12;
        int c = ck / 9, k = ck - c * 9;
        int jy = c * 18 + 2 * k;
        float vy = 0.f, vx = 0.f;
        if (m < 9)       { vy = ow[jy * 9 + m]; vx = ow[(jy + 1) * 9 + m]; }
        else if (m == 9) { vy = obv[jy];        vx = obv[jy + 1]; }
        g_sowH[i] = h2u(__floats2half2_rn(vy, vx));
    }
}

__global__ __launch_bounds__(256, 4)
void deform_fused_kernel(const float* __restrict__ x,
                         const float* __restrict__ db,
                         float* __restrict__ out)
{
    extern __shared__ float sm[];
    uint32_t* saf0W = (uint32_t*)sm + SAF0_F;
    uint32_t* safLW = (uint32_t*)sm + SAFL_F;
    __half*   saf0H = (__half*)saf0W;
    __half*   safLH = (__half*)safLW;
    float*    red   = sm + RED_F;
    float*    invS  = sm + INVS_F;

    const int t  = threadIdx.x;
    const int w0 = blockIdx.x * Pp;
    const int h  = blockIdx.y;
    const int b  = blockIdx.z;

    const int c  = t >> 2;
    const int pA = (t & 3) * 4;

    // ---- direct gmem patch loads -> splatted half2 regs ----
    __half2 sp[4][7];
    {
        const float* xc = x + ((size_t)(b * Cc + c)) * (Hh * Ww);
        const int gx0 = w0 + pA - 1;
        bool xv[7];
        #pragma unroll
        for (int s = 0; s < 7; s++) {
            int gx = gx0 + s;
            xv[s] = (gx >= 0) && (gx < Ww);
        }
        #pragma unroll
        for (int r = 0; r < 4; r++) {
            int gy = h - 1 + r;
            bool yv = (gy >= 0) && (gy < Hh);
            const float* xr = xc + gy * Ww + gx0;
            #pragma unroll
            for (int s = 0; s < 7; s++) {
                float v = (yv && xv[s]) ? __ldg(xr + s) : 0.0f;
                sp[r][s] = __float2half2_rn(v);
            }
        }
    }

    const uint32_t* wcH = g_sowH + c * 108;
    const int cb       = (c >> 1) * 18 + (c & 1) * 8;   // K' base, even
    const int lanebase = (pA & 7) * 4;
    const int regbase  = (pA >> 3);

    float sums[4] = {0.f, 0.f, 0.f, 0.f};

    // conv + exp for one tap k (compile-time k)
    auto convk = [&](int k, __half2 ee[4]) {
        uint4 wa = __ldg((const uint4*)(wcH + k * 12));
        uint4 wb = __ldg((const uint4*)(wcH + k * 12 + 4));
        uint2 wz = __ldg((const uint2*)(wcH + k * 12 + 8));
        __half2 w2[9] = {u2h(wa.x), u2h(wa.y), u2h(wa.z), u2h(wa.w),
                         u2h(wb.x), u2h(wb.y), u2h(wb.z), u2h(wb.w),
                         u2h(wz.x)};
        __half2 b2 = u2h(wz.y);
        __half2 e[4] = {b2, b2, b2, b2};
        #pragma unroll
        for (int r = 0; r < 3; r++)
            #pragma unroll
            for (int s = 0; s < 3; s++) {
                __half2 wv = w2[r * 3 + s];
                #pragma unroll
                for (int q = 0; q < 4; q++)
                    e[q] = __hfma2(wv, sp[r][s + q], e[q]);
            }
        #pragma unroll
        for (int q = 0; q < 4; q++) {
            ee[q] = h2exp(e[q]);                  // (ey, ex)
            float2 ef = __half22float2(ee[q]);
            sums[q] += ef.x + ef.y;
        }
    };

    // ---- 4 aligned pairs (k, k+1) -> packed STS.32 fragment stores ----
    #pragma unroll
    for (int i = 0; i < 4; i++) {
        const int k0 = 2 * i, k1 = 2 * i + 1;
        __half2 ee0[4], ee1[4];
        convk(k0, ee0);
        convk(k1, ee1);

        const int ck0   = cb + k0;                // even
        const int kb    = ck0 >> 4;
        const int c16   = ck0 & 15;
        const int tig   = (c16 >> 1) & 3;
        const int halfk = c16 >> 3;
        const int wbase = (kb * 32 + lanebase + tig) * 4 + regbase + halfk * 2;

        const int ky0 = k0 / 3, kx0 = k0 % 3;
        const int ky1 = k1 / 3, kx1 = k1 % 3;
        #pragma unroll
        for (int q = 0; q < 4; q++) {
            __half2 a00P = __lows2half2(sp[ky0][kx0 + q], sp[ky1][kx1 + q]);
            __half2 dh0 = __hsub2(sp[ky0][kx0 + q + 1], sp[ky0][kx0 + q]);
            __half2 dv0 = __hsub2(sp[ky0 + 1][kx0 + q], sp[ky0][kx0 + q]);
            __half2 dh1 = __hsub2(sp[ky1][kx1 + q + 1], sp[ky1][kx1 + q]);
            __half2 dv1 = __hsub2(sp[ky1 + 1][kx1 + q], sp[ky1][kx1 + q]);
            __half2 eyP = __lows2half2(ee0[q], ee1[q]);
            __half2 exP = __highs2half2(ee0[q], ee1[q]);
            __half2 dvP = __lows2half2(dv0, dv1);
            __half2 dhP = __lows2half2(dh0, dh1);
            __half2 LP  = __hfma2(exP, dhP, __hmul2(eyP, dvP));
            int wi = wbase + 16 * q;
            saf0W[wi] = h2u(a00P);
            safLW[wi] = h2u(LP);
        }
    }

    // ---- single k=8 (ky=2, kx=2) -> STS.16 ----
    {
        __half2 ee[4];
        convk(8, ee);
        const int cks   = (c >> 1) * 18 + 16 + (c & 1);
        const int kb    = cks >> 4;
        const int c16   = cks & 15;
        const int tig   = (c16 >> 1) & 3;
        const int halfk = c16 >> 3;
        const int hsel  = cks & 1;
        const int wbase = (kb * 32 + lanebase + tig) * 4 + regbase + halfk * 2;
        #pragma unroll
        for (int q = 0; q < 4; q++) {
            __half a00 = __low2half(sp[2][2 + q]);
            __half2 dh = __hsub2(sp[2][3 + q], sp[2][2 + q]);
            __half2 dv = __hsub2(sp[3][2 + q], sp[2][2 + q]);
            __half L = __hfma(__high2half(ee[q]), __low2half(dh),
                              __hmul(__low2half(ee[q]), __low2half(dv)));
            int hi = (wbase + 16 * q) * 2 + hsel;
            saf0H[hi] = a00;
            safLH[hi] = L;
        }
    }

    // ---- softmax denominator reduction ----
    #pragma unroll
    for (int off = 4; off <= 16; off <<= 1)
        #pragma unroll
        for (int q = 0; q < 4; q++)
            sums[q] += __shfl_xor_sync(0xffffffffu, sums[q], off);
    {
        int lane = t & 31, warp = t >> 5;
        if (lane < 4) {
            #pragma unroll
            for (int q = 0; q < 4; q++)
                red[warp * 16 + lane * 4 + q] = sums[q];
        }
    }
    __syncthreads();
    if (t < 16) {
        float s = 0.f;
        #pragma unroll
        for (int w = 0; w < 8; w++) s += red[w * 16 + t];
        invS[t] = 1.0f / s;
    }
    __syncthreads();   // also orders saf0/safL stores before GEMM reads

    // ---- Split GEMM: D = A0*B, DL = AL*B (shared B); 36 k-steps ----
    {
        const int nt = t >> 5;
        const int l  = t & 31;
        float d0 = 0.f, d1 = 0.f, d2 = 0.f, d3 = 0.f;
        float l0 = 0.f, l1 = 0.f, l2 = 0.f, l3 = 0.f;
        const uint32_t* bp  = g_bfragH + nt * (36 * 64) + l * 2;
        const uint32_t* a0p = saf0W + l * 4;
        const uint32_t* aLp = safLW + l * 4;

        #pragma unroll 4
        for (int kb = 0; kb < 36; kb++) {
            uint4 av0 = *(const uint4*)(a0p + kb * 128);
            uint4 avL = *(const uint4*)(aLp + kb * 128);
            uint2 bv  = __ldg((const uint2*)(bp + kb * 64));
            asm("mma.sync.aligned.m16n8k16.row.col.f32.f16.f16.f32 "
                "{%0,%1,%2,%3}, {%4,%5,%6,%7}, {%8,%9}, {%0,%1,%2,%3};"
                : "+f"(d0), "+f"(d1), "+f"(d2), "+f"(d3)
                : "r"(av0.x), "r"(av0.y), "r"(av0.z), "r"(av0.w),
                  "r"(bv.x), "r"(bv.y));
            asm("mma.sync.aligned.m16n8k16.row.col.f32.f16.f16.f32 "
                "{%0,%1,%2,%3}, {%4,%5,%6,%7}, {%8,%9}, {%0,%1,%2,%3};"
                : "+f"(l0), "+f"(l1), "+f"(l2), "+f"(l3)
                : "r"(avL.x), "r"(avL.y), "r"(avL.z), "r"(avL.w),
                  "r"(bv.x), "r"(bv.y));
        }

        // c0:(row g, col 2tig) c1:(g, 2tig+1) c2:(g+8, 2tig) c3:(g+8, 2tig+1)
        const int g = l >> 2, tig = l & 3;
        const int o = nt * 8 + tig * 2;
        float bb0 = __ldg(&db[o]), bb1 = __ldg(&db[o + 1]);
        float ivg  = invS[g];
        float ivg8 = invS[g + 8];
        size_t base = ((size_t)(b * CO + o) * Hh + h) * Ww + w0;
        out[base + g]               = d0 + ivg  * l0 + bb0;
        out[base + Hh * Ww + g]     = d1 + ivg  * l1 + bb1;
        out[base + g + 8]           = d2 + ivg8 * l2 + bb0;
        out[base + Hh * Ww + g + 8] = d3 + ivg8 * l3 + bb1;
    }
}

extern "C" void kernel_launch(void* const* d_in, const int* in_sizes, int n_in,
                              void* d_out, int out_size)
{
    const float* x   = (const float*)d_in[0];   // [8,64,128,128]
    const float* ow  = (const float*)d_in[1];   // [1152,1,3,3]
    const float* obv = (const float*)d_in[2];   // [1152]
    const float* dw  = (const float*)d_in[3];   // [64,64,3,3]
    const float* db  = (const float*)d_in[4];   // [64]
    float* out = (float*)d_out;                 // [8,64,128,128]

    cudaFuncSetAttribute(deform_fused_kernel,
                         cudaFuncAttributeMaxDynamicSharedMemorySize, SMEM_BYTES);

    prep_kernel<<<72, 256>>>(dw, ow, obv);

    dim3 grid(Ww / Pp, Hh, Bq);   // (8, 128, 8) = 8192 CTAs
    deform_fused_kernel<<<grid, 256, SMEM_BYTES>>>(x, db, out);
}